// round 15
// baseline (speedup 1.0000x reference)
#include <cuda_runtime.h>
#include <math.h>

// Problem dims
#define B   128
#define T   64
#define Xd  64
#define H   512
#define D   512
#define Z   64
#define KF  2
#define G   1536          // 3*H
#define BT  8192          // B*T
#define S   524288        // B*T*64
#define NBLK 128
#define SCAN_THREADS 512
#define SCAN_WARPS 16
#define SCAN_SMEM ((512*12 + SCAN_WARPS*12*128 + 16) * 4)
#define GEMM_SMEM (4 * 4224 * 4)   // As[2][32*132] + Ws[2][32*132]

typedef unsigned long long ull;

// ---------------- scratch ----------------
__device__ float  g_xT[BT * Xd];
__device__ float  g_gi[T * G * B];         // gi TRANSPOSED: [t][col][b]
__device__ float  g_h[(T + 1) * H * B];    // h TRANSPOSED: [t][k][b]
__device__ float  g_phi[BT * D];
__device__ float  g_head[BT * 128];
__device__ float  g_z[BT * Z];
__device__ float  g_WheadZ[128 * 512];
__device__ float  g_bheadZ[128];
__device__ float  g_WheadX[128 * 512];
__device__ float  g_bheadX[128];
__device__ double g_pz[2048];
__device__ double g_pn[2048];
__device__ double g_px[2048];
__device__ unsigned g_bar_count = 0;
__device__ unsigned g_bar_gen = 0;

// ---------------- helpers ----------------
__device__ __forceinline__ float fsigmoid_(float v) { return 1.0f / (1.0f + __expf(-v)); }
__device__ __forceinline__ float ftanh_(float v) { return 1.0f - 2.0f / (__expf(2.0f * v) + 1.0f); }
__device__ __forceinline__ float fsoftplus_(float v) {
    return (v > 20.0f) ? v : __logf(1.0f + __expf(v));
}

__device__ __forceinline__ void fma2(ull &a, ull x, ull y) {
    asm("fma.rn.f32x2 %0, %1, %2, %0;" : "+l"(a) : "l"(x), "l"(y));
}
__device__ __forceinline__ void add2(ull &a, ull x) {
    asm("add.rn.f32x2 %0, %0, %1;" : "+l"(a) : "l"(x));
}
__device__ __forceinline__ ull pack2(float lo, float hi) {
    ull r;
    asm("mov.b64 %0, {%1, %2};" : "=l"(r) : "f"(lo), "f"(hi));
    return r;
}
__device__ __forceinline__ float2 unpack2(ull v) {
    float2 r;
    asm("mov.b64 {%0, %1}, %2;" : "=f"(r.x), "=f"(r.y) : "l"(v));
    return r;
}

// monotonic-counter grid barrier
__device__ __forceinline__ void grid_barrier() {
    __threadfence();
    __syncthreads();
    if (threadIdx.x == 0) {
        volatile unsigned* vgen = &g_bar_gen;
        unsigned gen = *vgen;
        unsigned prev = atomicAdd(&g_bar_count, 1u);
        if ((prev & (NBLK - 1)) == (NBLK - 1)) {
            __threadfence();
            *vgen = gen + 1;
        } else {
            while (*vgen == gen) { }
            __threadfence();
        }
    }
    __syncthreads();
}

// ---------------- fused prep ----------------
__global__ void k_prep(const float* __restrict__ x,
                       const float* __restrict__ Wzm, const float* __restrict__ bzm,
                       const float* __restrict__ Wzs, const float* __restrict__ bzs,
                       const float* __restrict__ Wxm, const float* __restrict__ bxm,
                       const float* __restrict__ Wxs, const float* __restrict__ bxs,
                       float* __restrict__ xT, float* __restrict__ h0,
                       float* __restrict__ WhZ, float* __restrict__ bhZ,
                       float* __restrict__ WhX, float* __restrict__ bhX) {
    int i = blockIdx.x * blockDim.x + threadIdx.x;
    if (i < 524288) {
        int b = i >> 12;
        int r = i & 4095;
        int t = r >> 6;
        int xi = r & 63;
        xT[((t << 7) + b) * Xd + xi] = x[i];
    } else if (i < 589824) {
        h0[i - 524288] = 0.0f;
    } else if (i < 622592) {
        int q = i - 589824; WhZ[q] = Wzm[q];
    } else if (i < 655360) {
        int q = i - 622592; WhZ[32768 + q] = Wzs[q];
    } else if (i < 688128) {
        int q = i - 655360; WhX[q] = Wxm[q];
    } else if (i < 720896) {
        int q = i - 688128; WhX[32768 + q] = Wxs[q];
    } else if (i < 721152) {
        int q = i - 720896;
        if (q < 64)        bhZ[q] = bzm[q];
        else if (q < 128)  bhZ[q] = bzs[q - 64];
        else if (q < 192)  bhX[q - 128] = bxm[q - 128];
        else               bhX[q - 128] = bxs[q - 192];
    }
}

// ---------------- tiled GEMM 128x128, 32-k tiles, half-staged prefetch ----------------
__global__ void __launch_bounds__(256, 2)
k_gemm(const float* __restrict__ A, int lda,
       const float* __restrict__ W, int ldw,
       const float* __restrict__ bias,
       float* __restrict__ C, int ldc,
       int K, int act, int cmode) {
    extern __shared__ float gsm[];
    float* Asb0 = gsm;
    float* Asb1 = gsm + 4224;
    float* Wsb0 = gsm + 8448;
    float* Wsb1 = gsm + 12672;
    const int m0 = blockIdx.x * 128;
    const int n0 = blockIdx.y * 128;
    const int tx = threadIdx.x >> 4;
    const int ty = threadIdx.x & 15;
    const int lm = threadIdx.x >> 1;
    const int lq = (threadIdx.x & 1) * 8;

    const float* Aptr = A + (size_t)(m0 + lm) * lda + lq;
    const float* Wptr = W + (size_t)(n0 + lm) * ldw + lq;

    ull acc[8][4];
    #pragma unroll
    for (int i = 0; i < 8; i++)
        #pragma unroll
        for (int j = 0; j < 4; j++) acc[i][j] = 0ull;

    // prologue: tile 0 (k 0..31) into buffer 0
    #pragma unroll
    for (int ko = 0; ko < 32; ko += 16) {
        float4 a0 = *reinterpret_cast<const float4*>(Aptr + ko);
        float4 a1 = *reinterpret_cast<const float4*>(Aptr + ko + 4);
        float4 w0 = *reinterpret_cast<const float4*>(Wptr + ko);
        float4 w1 = *reinterpret_cast<const float4*>(Wptr + ko + 4);
        Asb0[(ko + lq + 0) * 132 + lm] = a0.x; Asb0[(ko + lq + 1) * 132 + lm] = a0.y;
        Asb0[(ko + lq + 2) * 132 + lm] = a0.z; Asb0[(ko + lq + 3) * 132 + lm] = a0.w;
        Asb0[(ko + lq + 4) * 132 + lm] = a1.x; Asb0[(ko + lq + 5) * 132 + lm] = a1.y;
        Asb0[(ko + lq + 6) * 132 + lm] = a1.z; Asb0[(ko + lq + 7) * 132 + lm] = a1.w;
        Wsb0[(ko + lq + 0) * 132 + lm] = w0.x; Wsb0[(ko + lq + 1) * 132 + lm] = w0.y;
        Wsb0[(ko + lq + 2) * 132 + lm] = w0.z; Wsb0[(ko + lq + 3) * 132 + lm] = w0.w;
        Wsb0[(ko + lq + 4) * 132 + lm] = w1.x; Wsb0[(ko + lq + 5) * 132 + lm] = w1.y;
        Wsb0[(ko + lq + 6) * 132 + lm] = w1.z; Wsb0[(ko + lq + 7) * 132 + lm] = w1.w;
    }
    __syncthreads();

    int p = 0;
    for (int k0 = 0; k0 < K; k0 += 32) {
        const bool more = (k0 + 32 < K);
        const float* Asp = p ? Asb1 : Asb0;
        const float* Wsp = p ? Wsb1 : Wsb0;
        float* Asq = p ? Asb0 : Asb1;
        float* Wsq = p ? Wsb0 : Wsb1;

        float4 a0, a1, w0, w1;
        if (more) {
            a0 = *reinterpret_cast<const float4*>(Aptr + k0 + 32);
            a1 = *reinterpret_cast<const float4*>(Aptr + k0 + 32 + 4);
            w0 = *reinterpret_cast<const float4*>(Wptr + k0 + 32);
            w1 = *reinterpret_cast<const float4*>(Wptr + k0 + 32 + 4);
        }
        // compute half 0 (k 0..15)
        #pragma unroll
        for (int k = 0; k < 16; k++) {
            float4 ap[2];
            #pragma unroll
            for (int mi = 0; mi < 2; mi++)
                ap[mi] = *reinterpret_cast<const float4*>(Asp + k * 132 + 4 * ty + 64 * mi);
            ulonglong2 bn0 = *reinterpret_cast<const ulonglong2*>(Wsp + k * 132 + tx * 8);
            ulonglong2 bn1 = *reinterpret_cast<const ulonglong2*>(Wsp + k * 132 + tx * 8 + 4);
            ull bp[4] = {bn0.x, bn0.y, bn1.x, bn1.y};
            #pragma unroll
            for (int mi = 0; mi < 2; mi++) {
                float aval[4] = {ap[mi].x, ap[mi].y, ap[mi].z, ap[mi].w};
                #pragma unroll
                for (int q = 0; q < 4; q++) {
                    ull ax = pack2(aval[q], aval[q]);
                    #pragma unroll
                    for (int np = 0; np < 4; np++) fma2(acc[4 * mi + q][np], ax, bp[np]);
                }
            }
        }
        if (more) {
            Asq[(lq + 0) * 132 + lm] = a0.x; Asq[(lq + 1) * 132 + lm] = a0.y;
            Asq[(lq + 2) * 132 + lm] = a0.z; Asq[(lq + 3) * 132 + lm] = a0.w;
            Asq[(lq + 4) * 132 + lm] = a1.x; Asq[(lq + 5) * 132 + lm] = a1.y;
            Asq[(lq + 6) * 132 + lm] = a1.z; Asq[(lq + 7) * 132 + lm] = a1.w;
            Wsq[(lq + 0) * 132 + lm] = w0.x; Wsq[(lq + 1) * 132 + lm] = w0.y;
            Wsq[(lq + 2) * 132 + lm] = w0.z; Wsq[(lq + 3) * 132 + lm] = w0.w;
            Wsq[(lq + 4) * 132 + lm] = w1.x; Wsq[(lq + 5) * 132 + lm] = w1.y;
            Wsq[(lq + 6) * 132 + lm] = w1.z; Wsq[(lq + 7) * 132 + lm] = w1.w;
            a0 = *reinterpret_cast<const float4*>(Aptr + k0 + 48);
            a1 = *reinterpret_cast<const float4*>(Aptr + k0 + 48 + 4);
            w0 = *reinterpret_cast<const float4*>(Wptr + k0 + 48);
            w1 = *reinterpret_cast<const float4*>(Wptr + k0 + 48 + 4);
        }
        // compute half 1 (k 16..31)
        #pragma unroll
        for (int k = 16; k < 32; k++) {
            float4 ap[2];
            #pragma unroll
            for (int mi = 0; mi < 2; mi++)
                ap[mi] = *reinterpret_cast<const float4*>(Asp + k * 132 + 4 * ty + 64 * mi);
            ulonglong2 bn0 = *reinterpret_cast<const ulonglong2*>(Wsp + k * 132 + tx * 8);
            ulonglong2 bn1 = *reinterpret_cast<const ulonglong2*>(Wsp + k * 132 + tx * 8 + 4);
            ull bp[4] = {bn0.x, bn0.y, bn1.x, bn1.y};
            #pragma unroll
            for (int mi = 0; mi < 2; mi++) {
                float aval[4] = {ap[mi].x, ap[mi].y, ap[mi].z, ap[mi].w};
                #pragma unroll
                for (int q = 0; q < 4; q++) {
                    ull ax = pack2(aval[q], aval[q]);
                    #pragma unroll
                    for (int np = 0; np < 4; np++) fma2(acc[4 * mi + q][np], ax, bp[np]);
                }
            }
        }
        if (more) {
            Asq[(16 + lq + 0) * 132 + lm] = a0.x; Asq[(16 + lq + 1) * 132 + lm] = a0.y;
            Asq[(16 + lq + 2) * 132 + lm] = a0.z; Asq[(16 + lq + 3) * 132 + lm] = a0.w;
            Asq[(16 + lq + 4) * 132 + lm] = a1.x; Asq[(16 + lq + 5) * 132 + lm] = a1.y;
            Asq[(16 + lq + 6) * 132 + lm] = a1.z; Asq[(16 + lq + 7) * 132 + lm] = a1.w;
            Wsq[(16 + lq + 0) * 132 + lm] = w0.x; Wsq[(16 + lq + 1) * 132 + lm] = w0.y;
            Wsq[(16 + lq + 2) * 132 + lm] = w0.z; Wsq[(16 + lq + 3) * 132 + lm] = w0.w;
            Wsq[(16 + lq + 4) * 132 + lm] = w1.x; Wsq[(16 + lq + 5) * 132 + lm] = w1.y;
            Wsq[(16 + lq + 6) * 132 + lm] = w1.z; Wsq[(16 + lq + 7) * 132 + lm] = w1.w;
            __syncthreads();
            p ^= 1;
        }
    }

    float cv[8][8];
    #pragma unroll
    for (int r = 0; r < 8; r++) {
        #pragma unroll
        for (int np = 0; np < 4; np++) {
            float2 pv = unpack2(acc[r][np]);
            float v0 = pv.x + bias[n0 + tx * 8 + 2 * np];
            float v1 = pv.y + bias[n0 + tx * 8 + 2 * np + 1];
            if (act == 1) { v0 = fmaxf(v0, 0.0f); v1 = fmaxf(v1, 0.0f); }
            cv[r][2 * np] = v0; cv[r][2 * np + 1] = v1;
        }
    }
    if (cmode == 0) {
        #pragma unroll
        for (int r = 0; r < 8; r++) {
            int m = m0 + 4 * ty + 64 * (r >> 2) + (r & 3);
            float4 s0 = make_float4(cv[r][0], cv[r][1], cv[r][2], cv[r][3]);
            float4 s1 = make_float4(cv[r][4], cv[r][5], cv[r][6], cv[r][7]);
            *reinterpret_cast<float4*>(C + (size_t)m * ldc + n0 + tx * 8)     = s0;
            *reinterpret_cast<float4*>(C + (size_t)m * ldc + n0 + tx * 8 + 4) = s1;
        }
    } else {
        const int t = blockIdx.x;
        #pragma unroll
        for (int j = 0; j < 8; j++) {
            int n = n0 + tx * 8 + j;
            size_t base = ((size_t)t * ldc + n) * B;
            #pragma unroll
            for (int mi = 0; mi < 2; mi++) {
                int m = 4 * ty + 64 * mi;
                *reinterpret_cast<float4*>(C + base + m) =
                    make_float4(cv[4 * mi][j], cv[4 * mi + 1][j],
                                cv[4 * mi + 2][j], cv[4 * mi + 3][j]);
            }
        }
    }
}

// ---------------- GEMM variant: A from transposed h, 32-k tiles, half-staged ----------------
__global__ void __launch_bounds__(256, 2)
k_gemm_ht(const float* __restrict__ hT,
          const float* __restrict__ W, int ldw,
          const float* __restrict__ bias,
          float* __restrict__ C, int ldc,
          int K, int act) {
    extern __shared__ float gsm[];
    float* Asb0 = gsm;
    float* Asb1 = gsm + 4224;
    float* Wsb0 = gsm + 8448;
    float* Wsb1 = gsm + 12672;
    const int m0 = blockIdx.x * 128;
    const int n0 = blockIdx.y * 128;
    const size_t slab = (size_t)(blockIdx.x + 1) * (H * B);
    const int tx = threadIdx.x >> 4;
    const int ty = threadIdx.x & 15;
    const int lm = threadIdx.x >> 1;
    const int lq = (threadIdx.x & 1) * 8;
    const int lk = threadIdx.x >> 4;
    const int lb = (threadIdx.x & 15) * 8;

    const float* Hptr = hT + slab + (size_t)lk * B + lb;
    const float* Wptr = W + (size_t)(n0 + lm) * ldw + lq;

    ull acc[8][4];
    #pragma unroll
    for (int i = 0; i < 8; i++)
        #pragma unroll
        for (int j = 0; j < 4; j++) acc[i][j] = 0ull;

    #pragma unroll
    for (int ko = 0; ko < 32; ko += 16) {
        float4 h0 = *reinterpret_cast<const float4*>(Hptr + (size_t)ko * B);
        float4 h1 = *reinterpret_cast<const float4*>(Hptr + (size_t)ko * B + 4);
        float4 w0 = *reinterpret_cast<const float4*>(Wptr + ko);
        float4 w1 = *reinterpret_cast<const float4*>(Wptr + ko + 4);
        *reinterpret_cast<float4*>(&Asb0[(ko + lk) * 132 + lb])     = h0;
        *reinterpret_cast<float4*>(&Asb0[(ko + lk) * 132 + lb + 4]) = h1;
        Wsb0[(ko + lq + 0) * 132 + lm] = w0.x; Wsb0[(ko + lq + 1) * 132 + lm] = w0.y;
        Wsb0[(ko + lq + 2) * 132 + lm] = w0.z; Wsb0[(ko + lq + 3) * 132 + lm] = w0.w;
        Wsb0[(ko + lq + 4) * 132 + lm] = w1.x; Wsb0[(ko + lq + 5) * 132 + lm] = w1.y;
        Wsb0[(ko + lq + 6) * 132 + lm] = w1.z; Wsb0[(ko + lq + 7) * 132 + lm] = w1.w;
    }
    __syncthreads();

    int p = 0;
    for (int k0 = 0; k0 < K; k0 += 32) {
        const bool more = (k0 + 32 < K);
        const float* Asp = p ? Asb1 : Asb0;
        const float* Wsp = p ? Wsb1 : Wsb0;
        float* Asq = p ? Asb0 : Asb1;
        float* Wsq = p ? Wsb0 : Wsb1;

        float4 h0, h1, w0, w1;
        if (more) {
            h0 = *reinterpret_cast<const float4*>(Hptr + (size_t)(k0 + 32) * B);
            h1 = *reinterpret_cast<const float4*>(Hptr + (size_t)(k0 + 32) * B + 4);
            w0 = *reinterpret_cast<const float4*>(Wptr + k0 + 32);
            w1 = *reinterpret_cast<const float4*>(Wptr + k0 + 32 + 4);
        }
        #pragma unroll
        for (int k = 0; k < 16; k++) {
            float4 ap[2];
            #pragma unroll
            for (int mi = 0; mi < 2; mi++)
                ap[mi] = *reinterpret_cast<const float4*>(Asp + k * 132 + 4 * ty + 64 * mi);
            ulonglong2 bn0 = *reinterpret_cast<const ulonglong2*>(Wsp + k * 132 + tx * 8);
            ulonglong2 bn1 = *reinterpret_cast<const ulonglong2*>(Wsp + k * 132 + tx * 8 + 4);
            ull bp[4] = {bn0.x, bn0.y, bn1.x, bn1.y};
            #pragma unroll
            for (int mi = 0; mi < 2; mi++) {
                float aval[4] = {ap[mi].x, ap[mi].y, ap[mi].z, ap[mi].w};
                #pragma unroll
                for (int q = 0; q < 4; q++) {
                    ull ax = pack2(aval[q], aval[q]);
                    #pragma unroll
                    for (int np = 0; np < 4; np++) fma2(acc[4 * mi + q][np], ax, bp[np]);
                }
            }
        }
        if (more) {
            *reinterpret_cast<float4*>(&Asq[lk * 132 + lb])     = h0;
            *reinterpret_cast<float4*>(&Asq[lk * 132 + lb + 4]) = h1;
            Wsq[(lq + 0) * 132 + lm] = w0.x; Wsq[(lq + 1) * 132 + lm] = w0.y;
            Wsq[(lq + 2) * 132 + lm] = w0.z; Wsq[(lq + 3) * 132 + lm] = w0.w;
            Wsq[(lq + 4) * 132 + lm] = w1.x; Wsq[(lq + 5) * 132 + lm] = w1.y;
            Wsq[(lq + 6) * 132 + lm] = w1.z; Wsq[(lq + 7) * 132 + lm] = w1.w;
            h0 = *reinterpret_cast<const float4*>(Hptr + (size_t)(k0 + 48) * B);
            h1 = *reinterpret_cast<const float4*>(Hptr + (size_t)(k0 + 48) * B + 4);
            w0 = *reinterpret_cast<const float4*>(Wptr + k0 + 48);
            w1 = *reinterpret_cast<const float4*>(Wptr + k0 + 48 + 4);
        }
        #pragma unroll
        for (int k = 16; k < 32; k++) {
            float4 ap[2];
            #pragma unroll
            for (int mi = 0; mi < 2; mi++)
                ap[mi] = *reinterpret_cast<const float4*>(Asp + k * 132 + 4 * ty + 64 * mi);
            ulonglong2 bn0 = *reinterpret_cast<const ulonglong2*>(Wsp + k * 132 + tx * 8);
            ulonglong2 bn1 = *reinterpret_cast<const ulonglong2*>(Wsp + k * 132 + tx * 8 + 4);
            ull bp[4] = {bn0.x, bn0.y, bn1.x, bn1.y};
            #pragma unroll
            for (int mi = 0; mi < 2; mi++) {
                float aval[4] = {ap[mi].x, ap[mi].y, ap[mi].z, ap[mi].w};
                #pragma unroll
                for (int q = 0; q < 4; q++) {
                    ull ax = pack2(aval[q], aval[q]);
                    #pragma unroll
                    for (int np = 0; np < 4; np++) fma2(acc[4 * mi + q][np], ax, bp[np]);
                }
            }
        }
        if (more) {
            *reinterpret_cast<float4*>(&Asq[(16 + lk) * 132 + lb])     = h0;
            *reinterpret_cast<float4*>(&Asq[(16 + lk) * 132 + lb + 4]) = h1;
            Wsq[(16 + lq + 0) * 132 + lm] = w0.x; Wsq[(16 + lq + 1) * 132 + lm] = w0.y;
            Wsq[(16 + lq + 2) * 132 + lm] = w0.z; Wsq[(16 + lq + 3) * 132 + lm] = w0.w;
            Wsq[(16 + lq + 4) * 132 + lm] = w1.x; Wsq[(16 + lq + 5) * 132 + lm] = w1.y;
            Wsq[(16 + lq + 6) * 132 + lm] = w1.z; Wsq[(16 + lq + 7) * 132 + lm] = w1.w;
            __syncthreads();
            p ^= 1;
        }
    }
    #pragma unroll
    for (int r = 0; r < 8; r++) {
        int m = m0 + 4 * ty + 64 * (r >> 2) + (r & 3);
        float cv[8];
        #pragma unroll
        for (int np = 0; np < 4; np++) {
            float2 pv = unpack2(acc[r][np]);
            float v0 = pv.x + bias[n0 + tx * 8 + 2 * np];
            float v1 = pv.y + bias[n0 + tx * 8 + 2 * np + 1];
            if (act == 1) { v0 = fmaxf(v0, 0.0f); v1 = fmaxf(v1, 0.0f); }
            cv[2 * np] = v0; cv[2 * np + 1] = v1;
        }
        float4 s0 = make_float4(cv[0], cv[1], cv[2], cv[3]);
        float4 s1 = make_float4(cv[4], cv[5], cv[6], cv[7]);
        *reinterpret_cast<float4*>(C + (size_t)m * ldc + n0 + tx * 8)     = s0;
        *reinterpret_cast<float4*>(C + (size_t)m * ldc + n0 + tx * 8 + 4) = s1;
    }
}

// ---------------- persistent GRU scan (R10 k-loop + packed ull reduction) ----------------
extern __shared__ float smem_dyn[];

__global__ void __launch_bounds__(SCAN_THREADS, 1)
k_gru_scan(const float* __restrict__ giT,  // [T][G][B]
           const float* __restrict__ Wh,   // [G, H]
           const float* __restrict__ bh,   // [G]
           float* __restrict__ hT)         // [(T+1), H, B]
{
    float* ws   = smem_dyn;                     // [512][12]
    ull*  redu  = (ull*)(ws + 512 * 12);        // [16][6][128] col-pairs packed
    float* sbh  = (float*)(redu + 16 * 6 * 128);// [12]
    const int tid  = threadIdx.x;
    const int warp = tid >> 5;
    const int lane = tid & 31;
    const int j0   = blockIdx.x * 4;

    for (int i = tid; i < 12 * 512; i += SCAN_THREADS) {
        int c = i >> 9, k = i & 511;
        ws[k * 12 + c] = Wh[((size_t)((c >> 2) * H + j0 + (c & 3))) * H + k];
    }
    if (tid < 12) sbh[tid] = bh[(tid >> 2) * H + j0 + (tid & 3)];
    __syncthreads();

    const int k0 = warp * 32;
    const int bbase = lane * 4;
    const int jp = tid >> 7;        // gate-phase col-pair (0/1), tid<256 only
    const int gb = tid & 127;
    const float br0 = sbh[2 * jp],     br1 = sbh[2 * jp + 1];
    const float bz0 = sbh[4 + 2 * jp], bz1 = sbh[4 + 2 * jp + 1];
    const float bn0 = sbh[8 + 2 * jp], bn1 = sbh[8 + 2 * jp + 1];

    for (int t = 0; t < T; t++) {
        const float* hprev = hT + (size_t)t * (H * B);

        // prefetch gate-phase operands (tid<256; coalesced)
        float ir0, ir1, iz0, iz1, in0, in1, hp0, hp1;
        if (tid < 256) {
            int ja = j0 + 2 * jp;
            size_t gib = ((size_t)t * G + ja) * B + gb;
            ir0 = giT[gib];                      ir1 = giT[gib + B];
            iz0 = giT[gib + (size_t)H * B];      iz1 = giT[gib + (size_t)H * B + B];
            in0 = giT[gib + (size_t)2 * H * B];  in1 = giT[gib + (size_t)2 * H * B + B];
            hp0 = hprev[(size_t)ja * B + gb];    hp1 = hprev[(size_t)(ja + 1) * B + gb];
        }

        ull acc[4][6];
        #pragma unroll
        for (int i = 0; i < 4; i++)
            #pragma unroll
            for (int cp = 0; cp < 6; cp++) acc[i][cp] = 0ull;

        #pragma unroll 4
        for (int kk = 0; kk < 32; kk++) {
            int k = k0 + kk;
            float4 hv = *reinterpret_cast<const float4*>(hprev + (size_t)k * B + bbase);
            ull h2[4];
            h2[0] = pack2(hv.x, hv.x);
            h2[1] = pack2(hv.y, hv.y);
            h2[2] = pack2(hv.z, hv.z);
            h2[3] = pack2(hv.w, hv.w);
            const float* wrow = ws + k * 12;
            #pragma unroll
            for (int cp = 0; cp < 6; cp++) {
                ull w2 = *reinterpret_cast<const ull*>(wrow + cp * 2);
                #pragma unroll
                for (int i = 0; i < 4; i++) fma2(acc[i][cp], h2[i], w2);
            }
        }

        // store packed col-pair partials: redu[(warp*6+cp)*128 + b]
        #pragma unroll
        for (int cp = 0; cp < 6; cp++) {
            ulonglong2* dst = reinterpret_cast<ulonglong2*>(
                redu + ((size_t)(warp * 6 + cp)) * 128 + bbase);
            dst[0] = make_ulonglong2(acc[0][cp], acc[1][cp]);
            dst[1] = make_ulonglong2(acc[2][cp], acc[3][cp]);
        }
        __syncthreads();

        // gate phase: 256 threads, each handles a col-pair x one b
        if (tid < 256) {
            ull gr2 = 0ull, gz2 = 0ull, gn2 = 0ull;
            #pragma unroll
            for (int w = 0; w < SCAN_WARPS; w++) {
                add2(gr2, redu[(w * 6 + jp) * 128 + gb]);
                add2(gz2, redu[(w * 6 + 2 + jp) * 128 + gb]);
                add2(gn2, redu[(w * 6 + 4 + jp) * 128 + gb]);
            }
            float2 gr = unpack2(gr2);
            float2 gz = unpack2(gz2);
            float2 gn = unpack2(gn2);
            int ja = j0 + 2 * jp;

            float r0 = fsigmoid_(ir0 + gr.x + br0);
            float u0 = fsigmoid_(iz0 + gz.x + bz0);
            float n0v = ftanh_(in0 + r0 * (gn.x + bn0));
            hT[((size_t)(t + 1) * H + ja) * B + gb] = (1.0f - u0) * n0v + u0 * hp0;

            float r1 = fsigmoid_(ir1 + gr.y + br1);
            float u1 = fsigmoid_(iz1 + gz.y + bz1);
            float n1v = ftanh_(in1 + r1 * (gn.y + bn1));
            hT[((size_t)(t + 1) * H + ja + 1) * B + gb] = (1.0f - u1) * n1v + u1 * hp1;
        }

        grid_barrier();
    }
}

// ---------------- encoder output: zm, zs, z, planar flow + kld_z partials ----------------
__global__ void k_flow_enc(const float* __restrict__ head,
                           const float* __restrict__ eps_enc,
                           const float* __restrict__ w_flow,
                           const float* __restrict__ b_flow,
                           const float* __restrict__ u_flow,
                           float* __restrict__ out,
                           float* __restrict__ z_all,
                           double* __restrict__ pz) {
    __shared__ float red[4][64];
    __shared__ double dred[256];
    int rl = threadIdx.x >> 6;
    int j = threadIdx.x & 63;
    int row = blockIdx.x * 4 + rl;       // t*B + b
    int t = row >> 7;
    int b = row & 127;

    float zm = fsigmoid_(head[row * 128 + j]);
    float zs = fsoftplus_(head[row * 128 + 64 + j]);
    float eps = eps_enc[b * (T * Z) + t * Z + j];
    float z = eps * zs + zm;

    #pragma unroll
    for (int k = 0; k < KF; k++) {
        red[rl][j] = z * w_flow[(t * KF + k) * Z + j];
        __syncthreads();
        #pragma unroll
        for (int s = 32; s > 0; s >>= 1) {
            if (j < s) red[rl][j] += red[rl][j + s];
            __syncthreads();
        }
        float sv = red[rl][0] + b_flow[t * KF + k];
        __syncthreads();
        z += u_flow[(t * KF + k) * Z + j] * ftanh_(sv);
    }

    int o = (b * T + t) * Z + j;
    out[2 + o]         = z;
    out[2 + S + o]     = zm;
    out[2 + 2 * S + o] = zs;
    z_all[row * Z + j] = z;

    float ez = __expf(zs);
    dred[threadIdx.x] = 1.0 + (double)zs - (double)zm * (double)zm - (double)ez;
    __syncthreads();
    for (int s = 128; s > 0; s >>= 1) {
        if (threadIdx.x < s) dred[threadIdx.x] += dred[threadIdx.x + s];
        __syncthreads();
    }
    if (threadIdx.x == 0) pz[blockIdx.x] = dred[0];
}

// ---------------- decoder output + nll/kld_x partials ----------------
__global__ void k_dec_out(const float* __restrict__ head,
                          const float* __restrict__ eps_dec,
                          const float* __restrict__ x,
                          float* __restrict__ out,
                          double* __restrict__ pn,
                          double* __restrict__ px) {
    __shared__ double sn[256];
    __shared__ double sk[256];
    int i = blockIdx.x * blockDim.x + threadIdx.x;
    int row = i >> 6;
    int j = i & 63;
    int t = row >> 7;
    int b = row & 127;
    float xm = fsigmoid_(head[row * 128 + j]);
    float xs = fsoftplus_(head[row * 128 + 64 + j]);
    int src = b * (T * Xd) + t * Xd + j;
    float eps = eps_dec[src];
    float xo = eps * xs + xm;
    int o = (b * T + t) * Xd + j;
    out[2 + 3 * S + o] = xo;
    out[2 + 4 * S + o] = xm;
    out[2 + 5 * S + o] = xs;

    float xv = x[src];
    float dq = (xv - xm) * __expf(-0.5f * xs);
    float ex = __expf(xs);
    sn[threadIdx.x] = (double)xs + (double)dq * (double)dq;
    sk[threadIdx.x] = 1.0 + (double)xs - (double)xm * (double)xm - (double)ex;
    __syncthreads();
    for (int s = 128; s > 0; s >>= 1) {
        if (threadIdx.x < s) {
            sn[threadIdx.x] += sn[threadIdx.x + s];
            sk[threadIdx.x] += sk[threadIdx.x + s];
        }
        __syncthreads();
    }
    if (threadIdx.x == 0) {
        pn[blockIdx.x] = sn[0];
        px[blockIdx.x] = sk[0];
    }
}

// ---------------- final deterministic reduction ----------------
__global__ void k_reduce_final(const double* __restrict__ pz,
                               const double* __restrict__ pn,
                               const double* __restrict__ px,
                               float* __restrict__ out) {
    __shared__ double sn[256];
    __shared__ double sk[256];
    double an = 0.0, ak = 0.0;
    for (int i = threadIdx.x; i < 2048; i += 256) {
        an += pn[i];
        ak += pz[i] + px[i];
    }
    sn[threadIdx.x] = an;
    sk[threadIdx.x] = ak;
    __syncthreads();
    for (int s = 128; s > 0; s >>= 1) {
        if (threadIdx.x < s) {
            sn[threadIdx.x] += sn[threadIdx.x + s];
            sk[threadIdx.x] += sk[threadIdx.x + s];
        }
        __syncthreads();
    }
    if (threadIdx.x == 0) {
        out[0] = (float)(0.5 * sn[0]);
        out[1] = (float)(-0.5 * sk[0]);
    }
}

// ---------------- launch ----------------
extern "C" void kernel_launch(void* const* d_in, const int* in_sizes, int n_in,
                              void* d_out, int out_size) {
    const float* x        = (const float*)d_in[0];
    const float* eps_enc  = (const float*)d_in[1];
    const float* eps_dec  = (const float*)d_in[2];
    const float* Wi_enc   = (const float*)d_in[3];
    const float* Wh_enc   = (const float*)d_in[4];
    const float* bi_enc   = (const float*)d_in[5];
    const float* bh_enc   = (const float*)d_in[6];
    const float* Wphi_enc = (const float*)d_in[7];
    const float* bphi_enc = (const float*)d_in[8];
    const float* W_zmean  = (const float*)d_in[9];
    const float* b_zmean  = (const float*)d_in[10];
    const float* W_zstd   = (const float*)d_in[11];
    const float* b_zstd   = (const float*)d_in[12];
    const float* w_flow   = (const float*)d_in[13];
    const float* b_flow   = (const float*)d_in[14];
    const float* u_flow   = (const float*)d_in[15];
    const float* Wi_dec   = (const float*)d_in[16];
    const float* Wh_dec   = (const float*)d_in[17];
    const float* bi_dec   = (const float*)d_in[18];
    const float* bh_dec   = (const float*)d_in[19];
    const float* Wphi_dec = (const float*)d_in[20];
    const float* bphi_dec = (const float*)d_in[21];
    const float* W_xmean  = (const float*)d_in[22];
    const float* b_xmean  = (const float*)d_in[23];
    const float* W_xstd   = (const float*)d_in[24];
    const float* b_xstd   = (const float*)d_in[25];
    float* out = (float*)d_out;

    float *p_xT, *p_gi, *p_h, *p_phi, *p_head, *p_z;
    float *p_WhZ, *p_bhZ, *p_WhX, *p_bhX;
    double *p_pz, *p_pn, *p_px;
    cudaGetSymbolAddress((void**)&p_xT,   g_xT);
    cudaGetSymbolAddress((void**)&p_gi,   g_gi);
    cudaGetSymbolAddress((void**)&p_h,    g_h);
    cudaGetSymbolAddress((void**)&p_phi,  g_phi);
    cudaGetSymbolAddress((void**)&p_head, g_head);
    cudaGetSymbolAddress((void**)&p_z,    g_z);
    cudaGetSymbolAddress((void**)&p_WhZ,  g_WheadZ);
    cudaGetSymbolAddress((void**)&p_bhZ,  g_bheadZ);
    cudaGetSymbolAddress((void**)&p_WhX,  g_WheadX);
    cudaGetSymbolAddress((void**)&p_bhX,  g_bheadX);
    cudaGetSymbolAddress((void**)&p_pz,   g_pz);
    cudaGetSymbolAddress((void**)&p_pn,   g_pn);
    cudaGetSymbolAddress((void**)&p_px,   g_px);

    cudaFuncSetAttribute(k_gru_scan, cudaFuncAttributeMaxDynamicSharedMemorySize, SCAN_SMEM);
    cudaFuncSetAttribute(k_gemm,    cudaFuncAttributeMaxDynamicSharedMemorySize, GEMM_SMEM);
    cudaFuncSetAttribute(k_gemm_ht, cudaFuncAttributeMaxDynamicSharedMemorySize, GEMM_SMEM);

    // 0) fused prep
    k_prep<<<(721152 + 255) / 256, 256>>>(x, W_zmean, b_zmean, W_zstd, b_zstd,
                                          W_xmean, b_xmean, W_xstd, b_xstd,
                                          p_xT, p_h, p_WhZ, p_bhZ, p_WhX, p_bhX);

    // 1) gi_enc -> transposed [t][col][b]
    {
        dim3 grid(BT / 128, G / 128);
        k_gemm<<<grid, 256, GEMM_SMEM>>>(p_xT, Xd, Wi_enc, Xd, bi_enc, p_gi, G, Xd, 0, 1);
    }
    // 2) encoder GRU scan
    k_gru_scan<<<NBLK, SCAN_THREADS, SCAN_SMEM>>>(p_gi, Wh_enc, bh_enc, p_h);

    // 3) phi_enc
    {
        dim3 grid(BT / 128, D / 128);
        k_gemm_ht<<<grid, 256, GEMM_SMEM>>>(p_h, Wphi_enc, H + Z, bphi_enc, p_phi, D, H, 1);
    }
    // 4) z heads
    {
        dim3 grid(BT / 128, 1);
        k_gemm<<<grid, 256, GEMM_SMEM>>>(p_phi, D, p_WhZ, D, p_bhZ, p_head, 128, D, 0, 0);
    }
    // 5) flow + z outputs + kld_z partials
    k_flow_enc<<<BT / 4, 256>>>(p_head, eps_enc, w_flow, b_flow, u_flow, out, p_z, p_pz);

    // 6) gi_dec -> transposed
    {
        dim3 grid(BT / 128, G / 128);
        k_gemm<<<grid, 256, GEMM_SMEM>>>(p_z, Z, Wi_dec, Z, bi_dec, p_gi, G, Z, 0, 1);
    }
    // 7) decoder GRU scan
    k_gru_scan<<<NBLK, SCAN_THREADS, SCAN_SMEM>>>(p_gi, Wh_dec, bh_dec, p_h);

    // 8) phi_dec
    {
        dim3 grid(BT / 128, D / 128);
        k_gemm_ht<<<grid, 256, GEMM_SMEM>>>(p_h, Wphi_dec, H, bphi_dec, p_phi, D, H, 1);
    }
    // 9) x heads
    {
        dim3 grid(BT / 128, 1);
        k_gemm<<<grid, 256, GEMM_SMEM>>>(p_phi, D, p_WhX, D, p_bhX, p_head, 128, D, 0, 0);
    }
    // 10) decoder outputs + nll/kld_x partials
    k_dec_out<<<S / 256, 256>>>(p_head, eps_dec, x, out, p_pn, p_px);

    // 11) final reduction
    k_reduce_final<<<1, 256>>>(p_pz, p_pn, p_px, out);
}

// round 16
// speedup vs baseline: 1.0069x; 1.0069x over previous
#include <cuda_runtime.h>
#include <math.h>

// Problem dims
#define B   128
#define T   64
#define Xd  64
#define H   512
#define D   512
#define Z   64
#define KF  2
#define G   1536          // 3*H
#define BT  8192          // B*T
#define S   524288        // B*T*64
#define NBLK 128
#define SCAN_THREADS 512
#define SCAN_WARPS 16
#define SCAN_SMEM ((512*12 + SCAN_WARPS*12*128 + 16) * 4)
#define GEMM_SMEM (4 * 4224 * 4)   // As[2][32*132] + Ws[2][32*132]

typedef unsigned long long ull;

// ---------------- scratch ----------------
__device__ float  g_xT[BT * Xd];
__device__ float  g_gi[T * G * B];         // gi TRANSPOSED: [t][col][b]
__device__ float  g_h[(T + 1) * H * B];    // h TRANSPOSED: [t][k][b]
__device__ float  g_phi[BT * D];
__device__ float  g_head[BT * 128];
__device__ float  g_z[BT * Z];
__device__ float  g_WheadZ[128 * 512];
__device__ float  g_bheadZ[128];
__device__ float  g_WheadX[128 * 512];
__device__ float  g_bheadX[128];
__device__ double g_pz[2048];
__device__ double g_pn[2048];
__device__ double g_px[2048];
__device__ unsigned g_bar_count = 0;
__device__ unsigned g_bar_gen = 0;

// ---------------- helpers ----------------
__device__ __forceinline__ float fsigmoid_(float v) { return 1.0f / (1.0f + __expf(-v)); }
__device__ __forceinline__ float ftanh_(float v) { return 1.0f - 2.0f / (__expf(2.0f * v) + 1.0f); }
__device__ __forceinline__ float fsoftplus_(float v) {
    return (v > 20.0f) ? v : __logf(1.0f + __expf(v));
}

__device__ __forceinline__ void fma2(ull &a, ull x, ull y) {
    asm("fma.rn.f32x2 %0, %1, %2, %0;" : "+l"(a) : "l"(x), "l"(y));
}
__device__ __forceinline__ ull pack2(float lo, float hi) {
    ull r;
    asm("mov.b64 %0, {%1, %2};" : "=l"(r) : "f"(lo), "f"(hi));
    return r;
}
__device__ __forceinline__ float2 unpack2(ull v) {
    float2 r;
    asm("mov.b64 {%0, %1}, %2;" : "=f"(r.x), "=f"(r.y) : "l"(v));
    return r;
}

// monotonic-counter grid barrier
__device__ __forceinline__ void grid_barrier() {
    __threadfence();
    __syncthreads();
    if (threadIdx.x == 0) {
        volatile unsigned* vgen = &g_bar_gen;
        unsigned gen = *vgen;
        unsigned prev = atomicAdd(&g_bar_count, 1u);
        if ((prev & (NBLK - 1)) == (NBLK - 1)) {
            __threadfence();
            *vgen = gen + 1;
        } else {
            while (*vgen == gen) { }
            __threadfence();
        }
    }
    __syncthreads();
}

// ---------------- fused prep ----------------
__global__ void k_prep(const float* __restrict__ x,
                       const float* __restrict__ Wzm, const float* __restrict__ bzm,
                       const float* __restrict__ Wzs, const float* __restrict__ bzs,
                       const float* __restrict__ Wxm, const float* __restrict__ bxm,
                       const float* __restrict__ Wxs, const float* __restrict__ bxs,
                       float* __restrict__ xT, float* __restrict__ h0,
                       float* __restrict__ WhZ, float* __restrict__ bhZ,
                       float* __restrict__ WhX, float* __restrict__ bhX) {
    int i = blockIdx.x * blockDim.x + threadIdx.x;
    if (i < 524288) {
        int b = i >> 12;
        int r = i & 4095;
        int t = r >> 6;
        int xi = r & 63;
        xT[((t << 7) + b) * Xd + xi] = x[i];
    } else if (i < 589824) {
        h0[i - 524288] = 0.0f;
    } else if (i < 622592) {
        int q = i - 589824; WhZ[q] = Wzm[q];
    } else if (i < 655360) {
        int q = i - 622592; WhZ[32768 + q] = Wzs[q];
    } else if (i < 688128) {
        int q = i - 655360; WhX[q] = Wxm[q];
    } else if (i < 720896) {
        int q = i - 688128; WhX[32768 + q] = Wxs[q];
    } else if (i < 721152) {
        int q = i - 720896;
        if (q < 64)        bhZ[q] = bzm[q];
        else if (q < 128)  bhZ[q] = bzs[q - 64];
        else if (q < 192)  bhX[q - 128] = bxm[q - 128];
        else               bhX[q - 128] = bxs[q - 192];
    }
}

// ---------------- tiled GEMM 128x128, 32-k tiles, half-staged prefetch ----------------
__global__ void __launch_bounds__(256, 2)
k_gemm(const float* __restrict__ A, int lda,
       const float* __restrict__ W, int ldw,
       const float* __restrict__ bias,
       float* __restrict__ C, int ldc,
       int K, int act, int cmode) {
    extern __shared__ float gsm[];
    float* Asb0 = gsm;
    float* Asb1 = gsm + 4224;
    float* Wsb0 = gsm + 8448;
    float* Wsb1 = gsm + 12672;
    const int m0 = blockIdx.x * 128;
    const int n0 = blockIdx.y * 128;
    const int tx = threadIdx.x >> 4;
    const int ty = threadIdx.x & 15;
    const int lm = threadIdx.x >> 1;
    const int lq = (threadIdx.x & 1) * 8;

    const float* Aptr = A + (size_t)(m0 + lm) * lda + lq;
    const float* Wptr = W + (size_t)(n0 + lm) * ldw + lq;

    ull acc[8][4];
    #pragma unroll
    for (int i = 0; i < 8; i++)
        #pragma unroll
        for (int j = 0; j < 4; j++) acc[i][j] = 0ull;

    #pragma unroll
    for (int ko = 0; ko < 32; ko += 16) {
        float4 a0 = *reinterpret_cast<const float4*>(Aptr + ko);
        float4 a1 = *reinterpret_cast<const float4*>(Aptr + ko + 4);
        float4 w0 = *reinterpret_cast<const float4*>(Wptr + ko);
        float4 w1 = *reinterpret_cast<const float4*>(Wptr + ko + 4);
        Asb0[(ko + lq + 0) * 132 + lm] = a0.x; Asb0[(ko + lq + 1) * 132 + lm] = a0.y;
        Asb0[(ko + lq + 2) * 132 + lm] = a0.z; Asb0[(ko + lq + 3) * 132 + lm] = a0.w;
        Asb0[(ko + lq + 4) * 132 + lm] = a1.x; Asb0[(ko + lq + 5) * 132 + lm] = a1.y;
        Asb0[(ko + lq + 6) * 132 + lm] = a1.z; Asb0[(ko + lq + 7) * 132 + lm] = a1.w;
        Wsb0[(ko + lq + 0) * 132 + lm] = w0.x; Wsb0[(ko + lq + 1) * 132 + lm] = w0.y;
        Wsb0[(ko + lq + 2) * 132 + lm] = w0.z; Wsb0[(ko + lq + 3) * 132 + lm] = w0.w;
        Wsb0[(ko + lq + 4) * 132 + lm] = w1.x; Wsb0[(ko + lq + 5) * 132 + lm] = w1.y;
        Wsb0[(ko + lq + 6) * 132 + lm] = w1.z; Wsb0[(ko + lq + 7) * 132 + lm] = w1.w;
    }
    __syncthreads();

    int p = 0;
    for (int k0 = 0; k0 < K; k0 += 32) {
        const bool more = (k0 + 32 < K);
        const float* Asp = p ? Asb1 : Asb0;
        const float* Wsp = p ? Wsb1 : Wsb0;
        float* Asq = p ? Asb0 : Asb1;
        float* Wsq = p ? Wsb0 : Wsb1;

        float4 a0, a1, w0, w1;
        if (more) {
            a0 = *reinterpret_cast<const float4*>(Aptr + k0 + 32);
            a1 = *reinterpret_cast<const float4*>(Aptr + k0 + 32 + 4);
            w0 = *reinterpret_cast<const float4*>(Wptr + k0 + 32);
            w1 = *reinterpret_cast<const float4*>(Wptr + k0 + 32 + 4);
        }
        #pragma unroll
        for (int k = 0; k < 16; k++) {
            float4 ap[2];
            #pragma unroll
            for (int mi = 0; mi < 2; mi++)
                ap[mi] = *reinterpret_cast<const float4*>(Asp + k * 132 + 4 * ty + 64 * mi);
            ulonglong2 bn0 = *reinterpret_cast<const ulonglong2*>(Wsp + k * 132 + tx * 8);
            ulonglong2 bn1 = *reinterpret_cast<const ulonglong2*>(Wsp + k * 132 + tx * 8 + 4);
            ull bp[4] = {bn0.x, bn0.y, bn1.x, bn1.y};
            #pragma unroll
            for (int mi = 0; mi < 2; mi++) {
                float aval[4] = {ap[mi].x, ap[mi].y, ap[mi].z, ap[mi].w};
                #pragma unroll
                for (int q = 0; q < 4; q++) {
                    ull ax = pack2(aval[q], aval[q]);
                    #pragma unroll
                    for (int np = 0; np < 4; np++) fma2(acc[4 * mi + q][np], ax, bp[np]);
                }
            }
        }
        if (more) {
            Asq[(lq + 0) * 132 + lm] = a0.x; Asq[(lq + 1) * 132 + lm] = a0.y;
            Asq[(lq + 2) * 132 + lm] = a0.z; Asq[(lq + 3) * 132 + lm] = a0.w;
            Asq[(lq + 4) * 132 + lm] = a1.x; Asq[(lq + 5) * 132 + lm] = a1.y;
            Asq[(lq + 6) * 132 + lm] = a1.z; Asq[(lq + 7) * 132 + lm] = a1.w;
            Wsq[(lq + 0) * 132 + lm] = w0.x; Wsq[(lq + 1) * 132 + lm] = w0.y;
            Wsq[(lq + 2) * 132 + lm] = w0.z; Wsq[(lq + 3) * 132 + lm] = w0.w;
            Wsq[(lq + 4) * 132 + lm] = w1.x; Wsq[(lq + 5) * 132 + lm] = w1.y;
            Wsq[(lq + 6) * 132 + lm] = w1.z; Wsq[(lq + 7) * 132 + lm] = w1.w;
            a0 = *reinterpret_cast<const float4*>(Aptr + k0 + 48);
            a1 = *reinterpret_cast<const float4*>(Aptr + k0 + 48 + 4);
            w0 = *reinterpret_cast<const float4*>(Wptr + k0 + 48);
            w1 = *reinterpret_cast<const float4*>(Wptr + k0 + 48 + 4);
        }
        #pragma unroll
        for (int k = 16; k < 32; k++) {
            float4 ap[2];
            #pragma unroll
            for (int mi = 0; mi < 2; mi++)
                ap[mi] = *reinterpret_cast<const float4*>(Asp + k * 132 + 4 * ty + 64 * mi);
            ulonglong2 bn0 = *reinterpret_cast<const ulonglong2*>(Wsp + k * 132 + tx * 8);
            ulonglong2 bn1 = *reinterpret_cast<const ulonglong2*>(Wsp + k * 132 + tx * 8 + 4);
            ull bp[4] = {bn0.x, bn0.y, bn1.x, bn1.y};
            #pragma unroll
            for (int mi = 0; mi < 2; mi++) {
                float aval[4] = {ap[mi].x, ap[mi].y, ap[mi].z, ap[mi].w};
                #pragma unroll
                for (int q = 0; q < 4; q++) {
                    ull ax = pack2(aval[q], aval[q]);
                    #pragma unroll
                    for (int np = 0; np < 4; np++) fma2(acc[4 * mi + q][np], ax, bp[np]);
                }
            }
        }
        if (more) {
            Asq[(16 + lq + 0) * 132 + lm] = a0.x; Asq[(16 + lq + 1) * 132 + lm] = a0.y;
            Asq[(16 + lq + 2) * 132 + lm] = a0.z; Asq[(16 + lq + 3) * 132 + lm] = a0.w;
            Asq[(16 + lq + 4) * 132 + lm] = a1.x; Asq[(16 + lq + 5) * 132 + lm] = a1.y;
            Asq[(16 + lq + 6) * 132 + lm] = a1.z; Asq[(16 + lq + 7) * 132 + lm] = a1.w;
            Wsq[(16 + lq + 0) * 132 + lm] = w0.x; Wsq[(16 + lq + 1) * 132 + lm] = w0.y;
            Wsq[(16 + lq + 2) * 132 + lm] = w0.z; Wsq[(16 + lq + 3) * 132 + lm] = w0.w;
            Wsq[(16 + lq + 4) * 132 + lm] = w1.x; Wsq[(16 + lq + 5) * 132 + lm] = w1.y;
            Wsq[(16 + lq + 6) * 132 + lm] = w1.z; Wsq[(16 + lq + 7) * 132 + lm] = w1.w;
            __syncthreads();
            p ^= 1;
        }
    }

    float cv[8][8];
    #pragma unroll
    for (int r = 0; r < 8; r++) {
        #pragma unroll
        for (int np = 0; np < 4; np++) {
            float2 pv = unpack2(acc[r][np]);
            float v0 = pv.x + bias[n0 + tx * 8 + 2 * np];
            float v1 = pv.y + bias[n0 + tx * 8 + 2 * np + 1];
            if (act == 1) { v0 = fmaxf(v0, 0.0f); v1 = fmaxf(v1, 0.0f); }
            cv[r][2 * np] = v0; cv[r][2 * np + 1] = v1;
        }
    }
    if (cmode == 0) {
        #pragma unroll
        for (int r = 0; r < 8; r++) {
            int m = m0 + 4 * ty + 64 * (r >> 2) + (r & 3);
            float4 s0 = make_float4(cv[r][0], cv[r][1], cv[r][2], cv[r][3]);
            float4 s1 = make_float4(cv[r][4], cv[r][5], cv[r][6], cv[r][7]);
            *reinterpret_cast<float4*>(C + (size_t)m * ldc + n0 + tx * 8)     = s0;
            *reinterpret_cast<float4*>(C + (size_t)m * ldc + n0 + tx * 8 + 4) = s1;
        }
    } else {
        const int t = blockIdx.x;
        #pragma unroll
        for (int j = 0; j < 8; j++) {
            int n = n0 + tx * 8 + j;
            size_t base = ((size_t)t * ldc + n) * B;
            #pragma unroll
            for (int mi = 0; mi < 2; mi++) {
                int m = 4 * ty + 64 * mi;
                *reinterpret_cast<float4*>(C + base + m) =
                    make_float4(cv[4 * mi][j], cv[4 * mi + 1][j],
                                cv[4 * mi + 2][j], cv[4 * mi + 3][j]);
            }
        }
    }
}

// ---------------- GEMM variant: A from transposed h, 32-k tiles, half-staged ----------------
__global__ void __launch_bounds__(256, 2)
k_gemm_ht(const float* __restrict__ hT,
          const float* __restrict__ W, int ldw,
          const float* __restrict__ bias,
          float* __restrict__ C, int ldc,
          int K, int act) {
    extern __shared__ float gsm[];
    float* Asb0 = gsm;
    float* Asb1 = gsm + 4224;
    float* Wsb0 = gsm + 8448;
    float* Wsb1 = gsm + 12672;
    const int m0 = blockIdx.x * 128;
    const int n0 = blockIdx.y * 128;
    const size_t slab = (size_t)(blockIdx.x + 1) * (H * B);
    const int tx = threadIdx.x >> 4;
    const int ty = threadIdx.x & 15;
    const int lm = threadIdx.x >> 1;
    const int lq = (threadIdx.x & 1) * 8;
    const int lk = threadIdx.x >> 4;
    const int lb = (threadIdx.x & 15) * 8;

    const float* Hptr = hT + slab + (size_t)lk * B + lb;
    const float* Wptr = W + (size_t)(n0 + lm) * ldw + lq;

    ull acc[8][4];
    #pragma unroll
    for (int i = 0; i < 8; i++)
        #pragma unroll
        for (int j = 0; j < 4; j++) acc[i][j] = 0ull;

    #pragma unroll
    for (int ko = 0; ko < 32; ko += 16) {
        float4 h0 = *reinterpret_cast<const float4*>(Hptr + (size_t)ko * B);
        float4 h1 = *reinterpret_cast<const float4*>(Hptr + (size_t)ko * B + 4);
        float4 w0 = *reinterpret_cast<const float4*>(Wptr + ko);
        float4 w1 = *reinterpret_cast<const float4*>(Wptr + ko + 4);
        *reinterpret_cast<float4*>(&Asb0[(ko + lk) * 132 + lb])     = h0;
        *reinterpret_cast<float4*>(&Asb0[(ko + lk) * 132 + lb + 4]) = h1;
        Wsb0[(ko + lq + 0) * 132 + lm] = w0.x; Wsb0[(ko + lq + 1) * 132 + lm] = w0.y;
        Wsb0[(ko + lq + 2) * 132 + lm] = w0.z; Wsb0[(ko + lq + 3) * 132 + lm] = w0.w;
        Wsb0[(ko + lq + 4) * 132 + lm] = w1.x; Wsb0[(ko + lq + 5) * 132 + lm] = w1.y;
        Wsb0[(ko + lq + 6) * 132 + lm] = w1.z; Wsb0[(ko + lq + 7) * 132 + lm] = w1.w;
    }
    __syncthreads();

    int p = 0;
    for (int k0 = 0; k0 < K; k0 += 32) {
        const bool more = (k0 + 32 < K);
        const float* Asp = p ? Asb1 : Asb0;
        const float* Wsp = p ? Wsb1 : Wsb0;
        float* Asq = p ? Asb0 : Asb1;
        float* Wsq = p ? Wsb0 : Wsb1;

        float4 h0, h1, w0, w1;
        if (more) {
            h0 = *reinterpret_cast<const float4*>(Hptr + (size_t)(k0 + 32) * B);
            h1 = *reinterpret_cast<const float4*>(Hptr + (size_t)(k0 + 32) * B + 4);
            w0 = *reinterpret_cast<const float4*>(Wptr + k0 + 32);
            w1 = *reinterpret_cast<const float4*>(Wptr + k0 + 32 + 4);
        }
        #pragma unroll
        for (int k = 0; k < 16; k++) {
            float4 ap[2];
            #pragma unroll
            for (int mi = 0; mi < 2; mi++)
                ap[mi] = *reinterpret_cast<const float4*>(Asp + k * 132 + 4 * ty + 64 * mi);
            ulonglong2 bn0 = *reinterpret_cast<const ulonglong2*>(Wsp + k * 132 + tx * 8);
            ulonglong2 bn1 = *reinterpret_cast<const ulonglong2*>(Wsp + k * 132 + tx * 8 + 4);
            ull bp[4] = {bn0.x, bn0.y, bn1.x, bn1.y};
            #pragma unroll
            for (int mi = 0; mi < 2; mi++) {
                float aval[4] = {ap[mi].x, ap[mi].y, ap[mi].z, ap[mi].w};
                #pragma unroll
                for (int q = 0; q < 4; q++) {
                    ull ax = pack2(aval[q], aval[q]);
                    #pragma unroll
                    for (int np = 0; np < 4; np++) fma2(acc[4 * mi + q][np], ax, bp[np]);
                }
            }
        }
        if (more) {
            *reinterpret_cast<float4*>(&Asq[lk * 132 + lb])     = h0;
            *reinterpret_cast<float4*>(&Asq[lk * 132 + lb + 4]) = h1;
            Wsq[(lq + 0) * 132 + lm] = w0.x; Wsq[(lq + 1) * 132 + lm] = w0.y;
            Wsq[(lq + 2) * 132 + lm] = w0.z; Wsq[(lq + 3) * 132 + lm] = w0.w;
            Wsq[(lq + 4) * 132 + lm] = w1.x; Wsq[(lq + 5) * 132 + lm] = w1.y;
            Wsq[(lq + 6) * 132 + lm] = w1.z; Wsq[(lq + 7) * 132 + lm] = w1.w;
            h0 = *reinterpret_cast<const float4*>(Hptr + (size_t)(k0 + 48) * B);
            h1 = *reinterpret_cast<const float4*>(Hptr + (size_t)(k0 + 48) * B + 4);
            w0 = *reinterpret_cast<const float4*>(Wptr + k0 + 48);
            w1 = *reinterpret_cast<const float4*>(Wptr + k0 + 48 + 4);
        }
        #pragma unroll
        for (int k = 16; k < 32; k++) {
            float4 ap[2];
            #pragma unroll
            for (int mi = 0; mi < 2; mi++)
                ap[mi] = *reinterpret_cast<const float4*>(Asp + k * 132 + 4 * ty + 64 * mi);
            ulonglong2 bn0 = *reinterpret_cast<const ulonglong2*>(Wsp + k * 132 + tx * 8);
            ulonglong2 bn1 = *reinterpret_cast<const ulonglong2*>(Wsp + k * 132 + tx * 8 + 4);
            ull bp[4] = {bn0.x, bn0.y, bn1.x, bn1.y};
            #pragma unroll
            for (int mi = 0; mi < 2; mi++) {
                float aval[4] = {ap[mi].x, ap[mi].y, ap[mi].z, ap[mi].w};
                #pragma unroll
                for (int q = 0; q < 4; q++) {
                    ull ax = pack2(aval[q], aval[q]);
                    #pragma unroll
                    for (int np = 0; np < 4; np++) fma2(acc[4 * mi + q][np], ax, bp[np]);
                }
            }
        }
        if (more) {
            *reinterpret_cast<float4*>(&Asq[(16 + lk) * 132 + lb])     = h0;
            *reinterpret_cast<float4*>(&Asq[(16 + lk) * 132 + lb + 4]) = h1;
            Wsq[(16 + lq + 0) * 132 + lm] = w0.x; Wsq[(16 + lq + 1) * 132 + lm] = w0.y;
            Wsq[(16 + lq + 2) * 132 + lm] = w0.z; Wsq[(16 + lq + 3) * 132 + lm] = w0.w;
            Wsq[(16 + lq + 4) * 132 + lm] = w1.x; Wsq[(16 + lq + 5) * 132 + lm] = w1.y;
            Wsq[(16 + lq + 6) * 132 + lm] = w1.z; Wsq[(16 + lq + 7) * 132 + lm] = w1.w;
            __syncthreads();
            p ^= 1;
        }
    }
    #pragma unroll
    for (int r = 0; r < 8; r++) {
        int m = m0 + 4 * ty + 64 * (r >> 2) + (r & 3);
        float cv[8];
        #pragma unroll
        for (int np = 0; np < 4; np++) {
            float2 pv = unpack2(acc[r][np]);
            float v0 = pv.x + bias[n0 + tx * 8 + 2 * np];
            float v1 = pv.y + bias[n0 + tx * 8 + 2 * np + 1];
            if (act == 1) { v0 = fmaxf(v0, 0.0f); v1 = fmaxf(v1, 0.0f); }
            cv[2 * np] = v0; cv[2 * np + 1] = v1;
        }
        float4 s0 = make_float4(cv[0], cv[1], cv[2], cv[3]);
        float4 s1 = make_float4(cv[4], cv[5], cv[6], cv[7]);
        *reinterpret_cast<float4*>(C + (size_t)m * ldc + n0 + tx * 8)     = s0;
        *reinterpret_cast<float4*>(C + (size_t)m * ldc + n0 + tx * 8 + 4) = s1;
    }
}

// ---------------- persistent GRU scan (exact R14 structure) ----------------
extern __shared__ float smem_dyn[];

__global__ void __launch_bounds__(SCAN_THREADS, 1)
k_gru_scan(const float* __restrict__ giT,  // [T][G][B]
           const float* __restrict__ Wh,   // [G, H]
           const float* __restrict__ bh,   // [G]
           float* __restrict__ hT)         // [(T+1), H, B]
{
    float* ws  = smem_dyn;                     // [512][12] : ws[k*12 + c], c = g*4+jj
    float* red = ws + 512 * 12;                // [16][12][128]
    float* sbh = red + SCAN_WARPS * 12 * 128;  // [12]
    const int tid  = threadIdx.x;
    const int warp = tid >> 5;
    const int lane = tid & 31;
    const int j0   = blockIdx.x * 4;

    for (int i = tid; i < 12 * 512; i += SCAN_THREADS) {
        int c = i >> 9, k = i & 511;
        ws[k * 12 + c] = Wh[((size_t)((c >> 2) * H + j0 + (c & 3))) * H + k];
    }
    if (tid < 12) sbh[tid] = bh[(tid >> 2) * H + j0 + (tid & 3)];
    __syncthreads();

    const int k0 = warp * 32;
    const int bbase = lane * 4;
    const int gjj = tid >> 7;       // gate-phase j
    const int gb  = tid & 127;      // gate-phase b
    const float bias_r = sbh[gjj];
    const float bias_z = sbh[4 + gjj];
    const float bias_n = sbh[8 + gjj];

    for (int t = 0; t < T; t++) {
        const float* hprev = hT + (size_t)t * (H * B);

        // prefetch gate-phase operands (coalesced; completes under the k-loop)
        size_t gibase = ((size_t)t * G + j0 + gjj) * B + gb;
        float ir  = giT[gibase];
        float iz  = giT[gibase + (size_t)H * B];
        float inn = giT[gibase + (size_t)2 * H * B];
        float hp  = hprev[(size_t)(j0 + gjj) * B + gb];

        ull acc[4][6];
        #pragma unroll
        for (int i = 0; i < 4; i++)
            #pragma unroll
            for (int cp = 0; cp < 6; cp++) acc[i][cp] = 0ull;

        #pragma unroll 4
        for (int kk = 0; kk < 32; kk++) {
            int k = k0 + kk;
            float4 hv = *reinterpret_cast<const float4*>(hprev + (size_t)k * B + bbase);
            ull h2[4];
            h2[0] = pack2(hv.x, hv.x);
            h2[1] = pack2(hv.y, hv.y);
            h2[2] = pack2(hv.z, hv.z);
            h2[3] = pack2(hv.w, hv.w);
            const float* wrow = ws + k * 12;
            #pragma unroll
            for (int cp = 0; cp < 6; cp++) {
                ull w2 = *reinterpret_cast<const ull*>(wrow + cp * 2);
                #pragma unroll
                for (int i = 0; i < 4; i++) fma2(acc[i][cp], h2[i], w2);
            }
        }

        #pragma unroll
        for (int cp = 0; cp < 6; cp++) {
            float2 v0 = unpack2(acc[0][cp]);
            float2 v1 = unpack2(acc[1][cp]);
            float2 v2 = unpack2(acc[2][cp]);
            float2 v3 = unpack2(acc[3][cp]);
            float4 a  = make_float4(v0.x, v1.x, v2.x, v3.x);
            float4 b4 = make_float4(v0.y, v1.y, v2.y, v3.y);
            *reinterpret_cast<float4*>(red + ((size_t)(warp * 12 + 2 * cp)) * B + bbase)     = a;
            *reinterpret_cast<float4*>(red + ((size_t)(warp * 12 + 2 * cp + 1)) * B + bbase) = b4;
        }
        __syncthreads();

        // gate phase: 512 outputs, one per thread
        {
            float gr = 0.f, gz = 0.f, gn = 0.f;
            #pragma unroll
            for (int w = 0; w < SCAN_WARPS; w++) {
                gr += red[(w * 12 + 0 + gjj) * B + gb];
                gz += red[(w * 12 + 4 + gjj) * B + gb];
                gn += red[(w * 12 + 8 + gjj) * B + gb];
            }
            float r = fsigmoid_(ir + gr + bias_r);
            float u = fsigmoid_(iz + gz + bias_z);
            float n = ftanh_(inn + r * (gn + bias_n));
            hT[((size_t)(t + 1) * H + j0 + gjj) * B + gb] = (1.0f - u) * n + u * hp;
        }

        grid_barrier();
    }
}

// ---------------- encoder output: zm, zs, z, planar flow + kld_z partials ----------------
__global__ void k_flow_enc(const float* __restrict__ head,
                           const float* __restrict__ eps_enc,
                           const float* __restrict__ w_flow,
                           const float* __restrict__ b_flow,
                           const float* __restrict__ u_flow,
                           float* __restrict__ out,
                           float* __restrict__ z_all,
                           double* __restrict__ pz) {
    __shared__ float red[4][64];
    __shared__ double dred[256];
    int rl = threadIdx.x >> 6;
    int j = threadIdx.x & 63;
    int row = blockIdx.x * 4 + rl;       // t*B + b
    int t = row >> 7;
    int b = row & 127;

    float zm = fsigmoid_(head[row * 128 + j]);
    float zs = fsoftplus_(head[row * 128 + 64 + j]);
    float eps = eps_enc[b * (T * Z) + t * Z + j];
    float z = eps * zs + zm;

    #pragma unroll
    for (int k = 0; k < KF; k++) {
        red[rl][j] = z * w_flow[(t * KF + k) * Z + j];
        __syncthreads();
        #pragma unroll
        for (int s = 32; s > 0; s >>= 1) {
            if (j < s) red[rl][j] += red[rl][j + s];
            __syncthreads();
        }
        float sv = red[rl][0] + b_flow[t * KF + k];
        __syncthreads();
        z += u_flow[(t * KF + k) * Z + j] * ftanh_(sv);
    }

    int o = (b * T + t) * Z + j;
    out[2 + o]         = z;
    out[2 + S + o]     = zm;
    out[2 + 2 * S + o] = zs;
    z_all[row * Z + j] = z;

    float ez = __expf(zs);
    dred[threadIdx.x] = 1.0 + (double)zs - (double)zm * (double)zm - (double)ez;
    __syncthreads();
    for (int s = 128; s > 0; s >>= 1) {
        if (threadIdx.x < s) dred[threadIdx.x] += dred[threadIdx.x + s];
        __syncthreads();
    }
    if (threadIdx.x == 0) pz[blockIdx.x] = dred[0];
}

// ---------------- decoder output + nll/kld_x partials ----------------
__global__ void k_dec_out(const float* __restrict__ head,
                          const float* __restrict__ eps_dec,
                          const float* __restrict__ x,
                          float* __restrict__ out,
                          double* __restrict__ pn,
                          double* __restrict__ px) {
    __shared__ double sn[256];
    __shared__ double sk[256];
    int i = blockIdx.x * blockDim.x + threadIdx.x;
    int row = i >> 6;
    int j = i & 63;
    int t = row >> 7;
    int b = row & 127;
    float xm = fsigmoid_(head[row * 128 + j]);
    float xs = fsoftplus_(head[row * 128 + 64 + j]);
    int src = b * (T * Xd) + t * Xd + j;
    float eps = eps_dec[src];
    float xo = eps * xs + xm;
    int o = (b * T + t) * Xd + j;
    out[2 + 3 * S + o] = xo;
    out[2 + 4 * S + o] = xm;
    out[2 + 5 * S + o] = xs;

    float xv = x[src];
    float dq = (xv - xm) * __expf(-0.5f * xs);
    float ex = __expf(xs);
    sn[threadIdx.x] = (double)xs + (double)dq * (double)dq;
    sk[threadIdx.x] = 1.0 + (double)xs - (double)xm * (double)xm - (double)ex;
    __syncthreads();
    for (int s = 128; s > 0; s >>= 1) {
        if (threadIdx.x < s) {
            sn[threadIdx.x] += sn[threadIdx.x + s];
            sk[threadIdx.x] += sk[threadIdx.x + s];
        }
        __syncthreads();
    }
    if (threadIdx.x == 0) {
        pn[blockIdx.x] = sn[0];
        px[blockIdx.x] = sk[0];
    }
}

// ---------------- final deterministic reduction ----------------
__global__ void k_reduce_final(const double* __restrict__ pz,
                               const double* __restrict__ pn,
                               const double* __restrict__ px,
                               float* __restrict__ out) {
    __shared__ double sn[256];
    __shared__ double sk[256];
    double an = 0.0, ak = 0.0;
    for (int i = threadIdx.x; i < 2048; i += 256) {
        an += pn[i];
        ak += pz[i] + px[i];
    }
    sn[threadIdx.x] = an;
    sk[threadIdx.x] = ak;
    __syncthreads();
    for (int s = 128; s > 0; s >>= 1) {
        if (threadIdx.x < s) {
            sn[threadIdx.x] += sn[threadIdx.x + s];
            sk[threadIdx.x] += sk[threadIdx.x + s];
        }
        __syncthreads();
    }
    if (threadIdx.x == 0) {
        out[0] = (float)(0.5 * sn[0]);
        out[1] = (float)(-0.5 * sk[0]);
    }
}

// ---------------- launch ----------------
extern "C" void kernel_launch(void* const* d_in, const int* in_sizes, int n_in,
                              void* d_out, int out_size) {
    const float* x        = (const float*)d_in[0];
    const float* eps_enc  = (const float*)d_in[1];
    const float* eps_dec  = (const float*)d_in[2];
    const float* Wi_enc   = (const float*)d_in[3];
    const float* Wh_enc   = (const float*)d_in[4];
    const float* bi_enc   = (const float*)d_in[5];
    const float* bh_enc   = (const float*)d_in[6];
    const float* Wphi_enc = (const float*)d_in[7];
    const float* bphi_enc = (const float*)d_in[8];
    const float* W_zmean  = (const float*)d_in[9];
    const float* b_zmean  = (const float*)d_in[10];
    const float* W_zstd   = (const float*)d_in[11];
    const float* b_zstd   = (const float*)d_in[12];
    const float* w_flow   = (const float*)d_in[13];
    const float* b_flow   = (const float*)d_in[14];
    const float* u_flow   = (const float*)d_in[15];
    const float* Wi_dec   = (const float*)d_in[16];
    const float* Wh_dec   = (const float*)d_in[17];
    const float* bi_dec   = (const float*)d_in[18];
    const float* bh_dec   = (const float*)d_in[19];
    const float* Wphi_dec = (const float*)d_in[20];
    const float* bphi_dec = (const float*)d_in[21];
    const float* W_xmean  = (const float*)d_in[22];
    const float* b_xmean  = (const float*)d_in[23];
    const float* W_xstd   = (const float*)d_in[24];
    const float* b_xstd   = (const float*)d_in[25];
    float* out = (float*)d_out;

    float *p_xT, *p_gi, *p_h, *p_phi, *p_head, *p_z;
    float *p_WhZ, *p_bhZ, *p_WhX, *p_bhX;
    double *p_pz, *p_pn, *p_px;
    cudaGetSymbolAddress((void**)&p_xT,   g_xT);
    cudaGetSymbolAddress((void**)&p_gi,   g_gi);
    cudaGetSymbolAddress((void**)&p_h,    g_h);
    cudaGetSymbolAddress((void**)&p_phi,  g_phi);
    cudaGetSymbolAddress((void**)&p_head, g_head);
    cudaGetSymbolAddress((void**)&p_z,    g_z);
    cudaGetSymbolAddress((void**)&p_WhZ,  g_WheadZ);
    cudaGetSymbolAddress((void**)&p_bhZ,  g_bheadZ);
    cudaGetSymbolAddress((void**)&p_WhX,  g_WheadX);
    cudaGetSymbolAddress((void**)&p_bhX,  g_bheadX);
    cudaGetSymbolAddress((void**)&p_pz,   g_pz);
    cudaGetSymbolAddress((void**)&p_pn,   g_pn);
    cudaGetSymbolAddress((void**)&p_px,   g_px);

    cudaFuncSetAttribute(k_gru_scan, cudaFuncAttributeMaxDynamicSharedMemorySize, SCAN_SMEM);
    cudaFuncSetAttribute(k_gemm,    cudaFuncAttributeMaxDynamicSharedMemorySize, GEMM_SMEM);
    cudaFuncSetAttribute(k_gemm_ht, cudaFuncAttributeMaxDynamicSharedMemorySize, GEMM_SMEM);

    // 0) fused prep
    k_prep<<<(721152 + 255) / 256, 256>>>(x, W_zmean, b_zmean, W_zstd, b_zstd,
                                          W_xmean, b_xmean, W_xstd, b_xstd,
                                          p_xT, p_h, p_WhZ, p_bhZ, p_WhX, p_bhX);

    // 1) gi_enc -> transposed [t][col][b]
    {
        dim3 grid(BT / 128, G / 128);
        k_gemm<<<grid, 256, GEMM_SMEM>>>(p_xT, Xd, Wi_enc, Xd, bi_enc, p_gi, G, Xd, 0, 1);
    }
    // 2) encoder GRU scan
    k_gru_scan<<<NBLK, SCAN_THREADS, SCAN_SMEM>>>(p_gi, Wh_enc, bh_enc, p_h);

    // 3) phi_enc
    {
        dim3 grid(BT / 128, D / 128);
        k_gemm_ht<<<grid, 256, GEMM_SMEM>>>(p_h, Wphi_enc, H + Z, bphi_enc, p_phi, D, H, 1);
    }
    // 4) z heads
    {
        dim3 grid(BT / 128, 1);
        k_gemm<<<grid, 256, GEMM_SMEM>>>(p_phi, D, p_WhZ, D, p_bhZ, p_head, 128, D, 0, 0);
    }
    // 5) flow + z outputs + kld_z partials
    k_flow_enc<<<BT / 4, 256>>>(p_head, eps_enc, w_flow, b_flow, u_flow, out, p_z, p_pz);

    // 6) gi_dec -> transposed
    {
        dim3 grid(BT / 128, G / 128);
        k_gemm<<<grid, 256, GEMM_SMEM>>>(p_z, Z, Wi_dec, Z, bi_dec, p_gi, G, Z, 0, 1);
    }
    // 7) decoder GRU scan
    k_gru_scan<<<NBLK, SCAN_THREADS, SCAN_SMEM>>>(p_gi, Wh_dec, bh_dec, p_h);

    // 8) phi_dec
    {
        dim3 grid(BT / 128, D / 128);
        k_gemm_ht<<<grid, 256, GEMM_SMEM>>>(p_h, Wphi_dec, H, bphi_dec, p_phi, D, H, 1);
    }
    // 9) x heads
    {
        dim3 grid(BT / 128, 1);
        k_gemm<<<grid, 256, GEMM_SMEM>>>(p_phi, D, p_WhX, D, p_bhX, p_head, 128, D, 0, 0);
    }
    // 10) decoder outputs + nll/kld_x partials
    k_dec_out<<<S / 256, 256>>>(p_head, eps_dec, x, out, p_pn, p_px);

    // 11) final reduction
    k_reduce_final<<<1, 256>>>(p_pz, p_pn, p_px, out);
}

// round 17
// speedup vs baseline: 1.0402x; 1.0330x over previous
#include <cuda_runtime.h>
#include <math.h>

// Problem dims
#define B   128
#define T   64
#define Xd  64
#define H   512
#define D   512
#define Z   64
#define KF  2
#define G   1536          // 3*H
#define BT  8192          // B*T
#define S   524288        // B*T*64
#define NBLK 128
#define SCAN_THREADS 512
#define SCAN_WARPS 16
#define SCAN_SMEM ((512*12 + SCAN_WARPS*12*128 + 16) * 4)
#define GEMM_SMEM (4 * 4224 * 4)   // As[2][32*132] + Ws[2][32*132]

typedef unsigned long long ull;

// ---------------- scratch ----------------
__device__ float  g_xT[BT * Xd];
__device__ float  g_gi[T * G * B];         // gi TRANSPOSED: [t][col][b]
__device__ float  g_h[(T + 1) * H * B];    // h TRANSPOSED: [t][k][b]
__device__ float  g_phi[BT * D];
__device__ float  g_head[BT * 128];
__device__ float  g_z[BT * Z];
__device__ float  g_WheadZ[128 * 512];
__device__ float  g_bheadZ[128];
__device__ float  g_WheadX[128 * 512];
__device__ float  g_bheadX[128];
__device__ double g_pz[2048];
__device__ double g_pn[2048];
__device__ double g_px[2048];
__device__ unsigned g_bar_count = 0;
__device__ unsigned g_bar_gen = 0;

// ---------------- helpers ----------------
__device__ __forceinline__ float fsigmoid_(float v) { return 1.0f / (1.0f + __expf(-v)); }
__device__ __forceinline__ float ftanh_(float v) { return 1.0f - 2.0f / (__expf(2.0f * v) + 1.0f); }
__device__ __forceinline__ float fsoftplus_(float v) {
    return (v > 20.0f) ? v : __logf(1.0f + __expf(v));
}

__device__ __forceinline__ void fma2(ull &a, ull x, ull y) {
    asm("fma.rn.f32x2 %0, %1, %2, %0;" : "+l"(a) : "l"(x), "l"(y));
}
__device__ __forceinline__ ull pack2(float lo, float hi) {
    ull r;
    asm("mov.b64 %0, {%1, %2};" : "=l"(r) : "f"(lo), "f"(hi));
    return r;
}
__device__ __forceinline__ float2 unpack2(ull v) {
    float2 r;
    asm("mov.b64 {%0, %1}, %2;" : "=f"(r.x), "=f"(r.y) : "l"(v));
    return r;
}

// monotonic-counter grid barrier
__device__ __forceinline__ void grid_barrier() {
    __threadfence();
    __syncthreads();
    if (threadIdx.x == 0) {
        volatile unsigned* vgen = &g_bar_gen;
        unsigned gen = *vgen;
        unsigned prev = atomicAdd(&g_bar_count, 1u);
        if ((prev & (NBLK - 1)) == (NBLK - 1)) {
            __threadfence();
            *vgen = gen + 1;
        } else {
            while (*vgen == gen) { }
            __threadfence();
        }
    }
    __syncthreads();
}

// ---------------- fused prep ----------------
__global__ void k_prep(const float* __restrict__ x,
                       const float* __restrict__ Wzm, const float* __restrict__ bzm,
                       const float* __restrict__ Wzs, const float* __restrict__ bzs,
                       const float* __restrict__ Wxm, const float* __restrict__ bxm,
                       const float* __restrict__ Wxs, const float* __restrict__ bxs,
                       float* __restrict__ xT, float* __restrict__ h0,
                       float* __restrict__ WhZ, float* __restrict__ bhZ,
                       float* __restrict__ WhX, float* __restrict__ bhX) {
    int i = blockIdx.x * blockDim.x + threadIdx.x;
    if (i < 524288) {
        int b = i >> 12;
        int r = i & 4095;
        int t = r >> 6;
        int xi = r & 63;
        xT[((t << 7) + b) * Xd + xi] = x[i];
    } else if (i < 589824) {
        h0[i - 524288] = 0.0f;
    } else if (i < 622592) {
        int q = i - 589824; WhZ[q] = Wzm[q];
    } else if (i < 655360) {
        int q = i - 622592; WhZ[32768 + q] = Wzs[q];
    } else if (i < 688128) {
        int q = i - 655360; WhX[q] = Wxm[q];
    } else if (i < 720896) {
        int q = i - 688128; WhX[32768 + q] = Wxs[q];
    } else if (i < 721152) {
        int q = i - 720896;
        if (q < 64)        bhZ[q] = bzm[q];
        else if (q < 128)  bhZ[q] = bzs[q - 64];
        else if (q < 192)  bhX[q - 128] = bxm[q - 128];
        else               bhX[q - 128] = bxs[q - 192];
    }
}

// ---------------- tiled GEMM 128x128, 32-k tiles, half-staged prefetch ----------------
__global__ void __launch_bounds__(256, 2)
k_gemm(const float* __restrict__ A, int lda,
       const float* __restrict__ W, int ldw,
       const float* __restrict__ bias,
       float* __restrict__ C, int ldc,
       int K, int act, int cmode) {
    extern __shared__ float gsm[];
    float* Asb0 = gsm;
    float* Asb1 = gsm + 4224;
    float* Wsb0 = gsm + 8448;
    float* Wsb1 = gsm + 12672;
    const int m0 = blockIdx.x * 128;
    const int n0 = blockIdx.y * 128;
    const int tx = threadIdx.x >> 4;
    const int ty = threadIdx.x & 15;
    const int lm = threadIdx.x >> 1;
    const int lq = (threadIdx.x & 1) * 8;

    const float* Aptr = A + (size_t)(m0 + lm) * lda + lq;
    const float* Wptr = W + (size_t)(n0 + lm) * ldw + lq;

    ull acc[8][4];
    #pragma unroll
    for (int i = 0; i < 8; i++)
        #pragma unroll
        for (int j = 0; j < 4; j++) acc[i][j] = 0ull;

    #pragma unroll
    for (int ko = 0; ko < 32; ko += 16) {
        float4 a0 = *reinterpret_cast<const float4*>(Aptr + ko);
        float4 a1 = *reinterpret_cast<const float4*>(Aptr + ko + 4);
        float4 w0 = *reinterpret_cast<const float4*>(Wptr + ko);
        float4 w1 = *reinterpret_cast<const float4*>(Wptr + ko + 4);
        Asb0[(ko + lq + 0) * 132 + lm] = a0.x; Asb0[(ko + lq + 1) * 132 + lm] = a0.y;
        Asb0[(ko + lq + 2) * 132 + lm] = a0.z; Asb0[(ko + lq + 3) * 132 + lm] = a0.w;
        Asb0[(ko + lq + 4) * 132 + lm] = a1.x; Asb0[(ko + lq + 5) * 132 + lm] = a1.y;
        Asb0[(ko + lq + 6) * 132 + lm] = a1.z; Asb0[(ko + lq + 7) * 132 + lm] = a1.w;
        Wsb0[(ko + lq + 0) * 132 + lm] = w0.x; Wsb0[(ko + lq + 1) * 132 + lm] = w0.y;
        Wsb0[(ko + lq + 2) * 132 + lm] = w0.z; Wsb0[(ko + lq + 3) * 132 + lm] = w0.w;
        Wsb0[(ko + lq + 4) * 132 + lm] = w1.x; Wsb0[(ko + lq + 5) * 132 + lm] = w1.y;
        Wsb0[(ko + lq + 6) * 132 + lm] = w1.z; Wsb0[(ko + lq + 7) * 132 + lm] = w1.w;
    }
    __syncthreads();

    int p = 0;
    for (int k0 = 0; k0 < K; k0 += 32) {
        const bool more = (k0 + 32 < K);
        const float* Asp = p ? Asb1 : Asb0;
        const float* Wsp = p ? Wsb1 : Wsb0;
        float* Asq = p ? Asb0 : Asb1;
        float* Wsq = p ? Wsb0 : Wsb1;

        float4 a0, a1, w0, w1;
        if (more) {
            a0 = *reinterpret_cast<const float4*>(Aptr + k0 + 32);
            a1 = *reinterpret_cast<const float4*>(Aptr + k0 + 32 + 4);
            w0 = *reinterpret_cast<const float4*>(Wptr + k0 + 32);
            w1 = *reinterpret_cast<const float4*>(Wptr + k0 + 32 + 4);
        }
        #pragma unroll
        for (int k = 0; k < 16; k++) {
            float4 ap[2];
            #pragma unroll
            for (int mi = 0; mi < 2; mi++)
                ap[mi] = *reinterpret_cast<const float4*>(Asp + k * 132 + 4 * ty + 64 * mi);
            ulonglong2 bn0 = *reinterpret_cast<const ulonglong2*>(Wsp + k * 132 + tx * 8);
            ulonglong2 bn1 = *reinterpret_cast<const ulonglong2*>(Wsp + k * 132 + tx * 8 + 4);
            ull bp[4] = {bn0.x, bn0.y, bn1.x, bn1.y};
            #pragma unroll
            for (int mi = 0; mi < 2; mi++) {
                float aval[4] = {ap[mi].x, ap[mi].y, ap[mi].z, ap[mi].w};
                #pragma unroll
                for (int q = 0; q < 4; q++) {
                    ull ax = pack2(aval[q], aval[q]);
                    #pragma unroll
                    for (int np = 0; np < 4; np++) fma2(acc[4 * mi + q][np], ax, bp[np]);
                }
            }
        }
        if (more) {
            Asq[(lq + 0) * 132 + lm] = a0.x; Asq[(lq + 1) * 132 + lm] = a0.y;
            Asq[(lq + 2) * 132 + lm] = a0.z; Asq[(lq + 3) * 132 + lm] = a0.w;
            Asq[(lq + 4) * 132 + lm] = a1.x; Asq[(lq + 5) * 132 + lm] = a1.y;
            Asq[(lq + 6) * 132 + lm] = a1.z; Asq[(lq + 7) * 132 + lm] = a1.w;
            Wsq[(lq + 0) * 132 + lm] = w0.x; Wsq[(lq + 1) * 132 + lm] = w0.y;
            Wsq[(lq + 2) * 132 + lm] = w0.z; Wsq[(lq + 3) * 132 + lm] = w0.w;
            Wsq[(lq + 4) * 132 + lm] = w1.x; Wsq[(lq + 5) * 132 + lm] = w1.y;
            Wsq[(lq + 6) * 132 + lm] = w1.z; Wsq[(lq + 7) * 132 + lm] = w1.w;
            a0 = *reinterpret_cast<const float4*>(Aptr + k0 + 48);
            a1 = *reinterpret_cast<const float4*>(Aptr + k0 + 48 + 4);
            w0 = *reinterpret_cast<const float4*>(Wptr + k0 + 48);
            w1 = *reinterpret_cast<const float4*>(Wptr + k0 + 48 + 4);
        }
        #pragma unroll
        for (int k = 16; k < 32; k++) {
            float4 ap[2];
            #pragma unroll
            for (int mi = 0; mi < 2; mi++)
                ap[mi] = *reinterpret_cast<const float4*>(Asp + k * 132 + 4 * ty + 64 * mi);
            ulonglong2 bn0 = *reinterpret_cast<const ulonglong2*>(Wsp + k * 132 + tx * 8);
            ulonglong2 bn1 = *reinterpret_cast<const ulonglong2*>(Wsp + k * 132 + tx * 8 + 4);
            ull bp[4] = {bn0.x, bn0.y, bn1.x, bn1.y};
            #pragma unroll
            for (int mi = 0; mi < 2; mi++) {
                float aval[4] = {ap[mi].x, ap[mi].y, ap[mi].z, ap[mi].w};
                #pragma unroll
                for (int q = 0; q < 4; q++) {
                    ull ax = pack2(aval[q], aval[q]);
                    #pragma unroll
                    for (int np = 0; np < 4; np++) fma2(acc[4 * mi + q][np], ax, bp[np]);
                }
            }
        }
        if (more) {
            Asq[(16 + lq + 0) * 132 + lm] = a0.x; Asq[(16 + lq + 1) * 132 + lm] = a0.y;
            Asq[(16 + lq + 2) * 132 + lm] = a0.z; Asq[(16 + lq + 3) * 132 + lm] = a0.w;
            Asq[(16 + lq + 4) * 132 + lm] = a1.x; Asq[(16 + lq + 5) * 132 + lm] = a1.y;
            Asq[(16 + lq + 6) * 132 + lm] = a1.z; Asq[(16 + lq + 7) * 132 + lm] = a1.w;
            Wsq[(16 + lq + 0) * 132 + lm] = w0.x; Wsq[(16 + lq + 1) * 132 + lm] = w0.y;
            Wsq[(16 + lq + 2) * 132 + lm] = w0.z; Wsq[(16 + lq + 3) * 132 + lm] = w0.w;
            Wsq[(16 + lq + 4) * 132 + lm] = w1.x; Wsq[(16 + lq + 5) * 132 + lm] = w1.y;
            Wsq[(16 + lq + 6) * 132 + lm] = w1.z; Wsq[(16 + lq + 7) * 132 + lm] = w1.w;
            __syncthreads();
            p ^= 1;
        }
    }

    float cv[8][8];
    #pragma unroll
    for (int r = 0; r < 8; r++) {
        #pragma unroll
        for (int np = 0; np < 4; np++) {
            float2 pv = unpack2(acc[r][np]);
            float v0 = pv.x + bias[n0 + tx * 8 + 2 * np];
            float v1 = pv.y + bias[n0 + tx * 8 + 2 * np + 1];
            if (act == 1) { v0 = fmaxf(v0, 0.0f); v1 = fmaxf(v1, 0.0f); }
            cv[r][2 * np] = v0; cv[r][2 * np + 1] = v1;
        }
    }
    if (cmode == 0) {
        #pragma unroll
        for (int r = 0; r < 8; r++) {
            int m = m0 + 4 * ty + 64 * (r >> 2) + (r & 3);
            float4 s0 = make_float4(cv[r][0], cv[r][1], cv[r][2], cv[r][3]);
            float4 s1 = make_float4(cv[r][4], cv[r][5], cv[r][6], cv[r][7]);
            *reinterpret_cast<float4*>(C + (size_t)m * ldc + n0 + tx * 8)     = s0;
            *reinterpret_cast<float4*>(C + (size_t)m * ldc + n0 + tx * 8 + 4) = s1;
        }
    } else {
        const int t = blockIdx.x;
        #pragma unroll
        for (int j = 0; j < 8; j++) {
            int n = n0 + tx * 8 + j;
            size_t base = ((size_t)t * ldc + n) * B;
            #pragma unroll
            for (int mi = 0; mi < 2; mi++) {
                int m = 4 * ty + 64 * mi;
                *reinterpret_cast<float4*>(C + base + m) =
                    make_float4(cv[4 * mi][j], cv[4 * mi + 1][j],
                                cv[4 * mi + 2][j], cv[4 * mi + 3][j]);
            }
        }
    }
}

// ---------------- GEMM variant: A from transposed h, 32-k tiles, half-staged ----------------
__global__ void __launch_bounds__(256, 2)
k_gemm_ht(const float* __restrict__ hT,
          const float* __restrict__ W, int ldw,
          const float* __restrict__ bias,
          float* __restrict__ C, int ldc,
          int K, int act) {
    extern __shared__ float gsm[];
    float* Asb0 = gsm;
    float* Asb1 = gsm + 4224;
    float* Wsb0 = gsm + 8448;
    float* Wsb1 = gsm + 12672;
    const int m0 = blockIdx.x * 128;
    const int n0 = blockIdx.y * 128;
    const size_t slab = (size_t)(blockIdx.x + 1) * (H * B);
    const int tx = threadIdx.x >> 4;
    const int ty = threadIdx.x & 15;
    const int lm = threadIdx.x >> 1;
    const int lq = (threadIdx.x & 1) * 8;
    const int lk = threadIdx.x >> 4;
    const int lb = (threadIdx.x & 15) * 8;

    const float* Hptr = hT + slab + (size_t)lk * B + lb;
    const float* Wptr = W + (size_t)(n0 + lm) * ldw + lq;

    ull acc[8][4];
    #pragma unroll
    for (int i = 0; i < 8; i++)
        #pragma unroll
        for (int j = 0; j < 4; j++) acc[i][j] = 0ull;

    #pragma unroll
    for (int ko = 0; ko < 32; ko += 16) {
        float4 h0 = *reinterpret_cast<const float4*>(Hptr + (size_t)ko * B);
        float4 h1 = *reinterpret_cast<const float4*>(Hptr + (size_t)ko * B + 4);
        float4 w0 = *reinterpret_cast<const float4*>(Wptr + ko);
        float4 w1 = *reinterpret_cast<const float4*>(Wptr + ko + 4);
        *reinterpret_cast<float4*>(&Asb0[(ko + lk) * 132 + lb])     = h0;
        *reinterpret_cast<float4*>(&Asb0[(ko + lk) * 132 + lb + 4]) = h1;
        Wsb0[(ko + lq + 0) * 132 + lm] = w0.x; Wsb0[(ko + lq + 1) * 132 + lm] = w0.y;
        Wsb0[(ko + lq + 2) * 132 + lm] = w0.z; Wsb0[(ko + lq + 3) * 132 + lm] = w0.w;
        Wsb0[(ko + lq + 4) * 132 + lm] = w1.x; Wsb0[(ko + lq + 5) * 132 + lm] = w1.y;
        Wsb0[(ko + lq + 6) * 132 + lm] = w1.z; Wsb0[(ko + lq + 7) * 132 + lm] = w1.w;
    }
    __syncthreads();

    int p = 0;
    for (int k0 = 0; k0 < K; k0 += 32) {
        const bool more = (k0 + 32 < K);
        const float* Asp = p ? Asb1 : Asb0;
        const float* Wsp = p ? Wsb1 : Wsb0;
        float* Asq = p ? Asb0 : Asb1;
        float* Wsq = p ? Wsb0 : Wsb1;

        float4 h0, h1, w0, w1;
        if (more) {
            h0 = *reinterpret_cast<const float4*>(Hptr + (size_t)(k0 + 32) * B);
            h1 = *reinterpret_cast<const float4*>(Hptr + (size_t)(k0 + 32) * B + 4);
            w0 = *reinterpret_cast<const float4*>(Wptr + k0 + 32);
            w1 = *reinterpret_cast<const float4*>(Wptr + k0 + 32 + 4);
        }
        #pragma unroll
        for (int k = 0; k < 16; k++) {
            float4 ap[2];
            #pragma unroll
            for (int mi = 0; mi < 2; mi++)
                ap[mi] = *reinterpret_cast<const float4*>(Asp + k * 132 + 4 * ty + 64 * mi);
            ulonglong2 bn0 = *reinterpret_cast<const ulonglong2*>(Wsp + k * 132 + tx * 8);
            ulonglong2 bn1 = *reinterpret_cast<const ulonglong2*>(Wsp + k * 132 + tx * 8 + 4);
            ull bp[4] = {bn0.x, bn0.y, bn1.x, bn1.y};
            #pragma unroll
            for (int mi = 0; mi < 2; mi++) {
                float aval[4] = {ap[mi].x, ap[mi].y, ap[mi].z, ap[mi].w};
                #pragma unroll
                for (int q = 0; q < 4; q++) {
                    ull ax = pack2(aval[q], aval[q]);
                    #pragma unroll
                    for (int np = 0; np < 4; np++) fma2(acc[4 * mi + q][np], ax, bp[np]);
                }
            }
        }
        if (more) {
            *reinterpret_cast<float4*>(&Asq[lk * 132 + lb])     = h0;
            *reinterpret_cast<float4*>(&Asq[lk * 132 + lb + 4]) = h1;
            Wsq[(lq + 0) * 132 + lm] = w0.x; Wsq[(lq + 1) * 132 + lm] = w0.y;
            Wsq[(lq + 2) * 132 + lm] = w0.z; Wsq[(lq + 3) * 132 + lm] = w0.w;
            Wsq[(lq + 4) * 132 + lm] = w1.x; Wsq[(lq + 5) * 132 + lm] = w1.y;
            Wsq[(lq + 6) * 132 + lm] = w1.z; Wsq[(lq + 7) * 132 + lm] = w1.w;
            h0 = *reinterpret_cast<const float4*>(Hptr + (size_t)(k0 + 48) * B);
            h1 = *reinterpret_cast<const float4*>(Hptr + (size_t)(k0 + 48) * B + 4);
            w0 = *reinterpret_cast<const float4*>(Wptr + k0 + 48);
            w1 = *reinterpret_cast<const float4*>(Wptr + k0 + 48 + 4);
        }
        #pragma unroll
        for (int k = 16; k < 32; k++) {
            float4 ap[2];
            #pragma unroll
            for (int mi = 0; mi < 2; mi++)
                ap[mi] = *reinterpret_cast<const float4*>(Asp + k * 132 + 4 * ty + 64 * mi);
            ulonglong2 bn0 = *reinterpret_cast<const ulonglong2*>(Wsp + k * 132 + tx * 8);
            ulonglong2 bn1 = *reinterpret_cast<const ulonglong2*>(Wsp + k * 132 + tx * 8 + 4);
            ull bp[4] = {bn0.x, bn0.y, bn1.x, bn1.y};
            #pragma unroll
            for (int mi = 0; mi < 2; mi++) {
                float aval[4] = {ap[mi].x, ap[mi].y, ap[mi].z, ap[mi].w};
                #pragma unroll
                for (int q = 0; q < 4; q++) {
                    ull ax = pack2(aval[q], aval[q]);
                    #pragma unroll
                    for (int np = 0; np < 4; np++) fma2(acc[4 * mi + q][np], ax, bp[np]);
                }
            }
        }
        if (more) {
            *reinterpret_cast<float4*>(&Asq[(16 + lk) * 132 + lb])     = h0;
            *reinterpret_cast<float4*>(&Asq[(16 + lk) * 132 + lb + 4]) = h1;
            Wsq[(16 + lq + 0) * 132 + lm] = w0.x; Wsq[(16 + lq + 1) * 132 + lm] = w0.y;
            Wsq[(16 + lq + 2) * 132 + lm] = w0.z; Wsq[(16 + lq + 3) * 132 + lm] = w0.w;
            Wsq[(16 + lq + 4) * 132 + lm] = w1.x; Wsq[(16 + lq + 5) * 132 + lm] = w1.y;
            Wsq[(16 + lq + 6) * 132 + lm] = w1.z; Wsq[(16 + lq + 7) * 132 + lm] = w1.w;
            __syncthreads();
            p ^= 1;
        }
    }
    #pragma unroll
    for (int r = 0; r < 8; r++) {
        int m = m0 + 4 * ty + 64 * (r >> 2) + (r & 3);
        float cv[8];
        #pragma unroll
        for (int np = 0; np < 4; np++) {
            float2 pv = unpack2(acc[r][np]);
            float v0 = pv.x + bias[n0 + tx * 8 + 2 * np];
            float v1 = pv.y + bias[n0 + tx * 8 + 2 * np + 1];
            if (act == 1) { v0 = fmaxf(v0, 0.0f); v1 = fmaxf(v1, 0.0f); }
            cv[2 * np] = v0; cv[2 * np + 1] = v1;
        }
        float4 s0 = make_float4(cv[0], cv[1], cv[2], cv[3]);
        float4 s1 = make_float4(cv[4], cv[5], cv[6], cv[7]);
        *reinterpret_cast<float4*>(C + (size_t)m * ldc + n0 + tx * 8)     = s0;
        *reinterpret_cast<float4*>(C + (size_t)m * ldc + n0 + tx * 8 + 4) = s1;
    }
}

// ---------------- head GEMM: 64x128 tile, K=512, high occupancy ----------------
// C[m][n] = A[m][:] . W[n][:] + bias[n], m-tile 64 (grid = BT/64 = 128 blocks)
__global__ void __launch_bounds__(256, 3)
k_gemm_h64(const float* __restrict__ A,
           const float* __restrict__ W,
           const float* __restrict__ bias,
           float* __restrict__ C) {
    __shared__ float As[2][16 * 68];
    __shared__ float Ws[2][16 * 132];
    const int m0 = blockIdx.x * 64;
    const int tx = threadIdx.x >> 4;        // n group 0..15
    const int ty = threadIdx.x & 15;        // m group 0..15
    const int am = threadIdx.x >> 2;        // A-load row 0..63
    const int aq = (threadIdx.x & 3) * 4;   // A-load k offset
    const int lm = threadIdx.x >> 1;        // W-load row 0..127
    const int lq = (threadIdx.x & 1) * 8;

    const float* Aptr = A + (size_t)(m0 + am) * D + aq;
    const float* Wptr = W + (size_t)lm * D + lq;

    ull acc[4][4];
    #pragma unroll
    for (int i = 0; i < 4; i++)
        #pragma unroll
        for (int j = 0; j < 4; j++) acc[i][j] = 0ull;

    {
        float4 a0 = *reinterpret_cast<const float4*>(Aptr);
        float4 w0 = *reinterpret_cast<const float4*>(Wptr);
        float4 w1 = *reinterpret_cast<const float4*>(Wptr + 4);
        As[0][(aq + 0) * 68 + am] = a0.x; As[0][(aq + 1) * 68 + am] = a0.y;
        As[0][(aq + 2) * 68 + am] = a0.z; As[0][(aq + 3) * 68 + am] = a0.w;
        Ws[0][(lq + 0) * 132 + lm] = w0.x; Ws[0][(lq + 1) * 132 + lm] = w0.y;
        Ws[0][(lq + 2) * 132 + lm] = w0.z; Ws[0][(lq + 3) * 132 + lm] = w0.w;
        Ws[0][(lq + 4) * 132 + lm] = w1.x; Ws[0][(lq + 5) * 132 + lm] = w1.y;
        Ws[0][(lq + 6) * 132 + lm] = w1.z; Ws[0][(lq + 7) * 132 + lm] = w1.w;
    }
    __syncthreads();

    int p = 0;
    for (int k0 = 0; k0 < D; k0 += 16) {
        const bool more = (k0 + 16 < D);
        float4 a0, w0, w1;
        if (more) {
            a0 = *reinterpret_cast<const float4*>(Aptr + k0 + 16);
            w0 = *reinterpret_cast<const float4*>(Wptr + k0 + 16);
            w1 = *reinterpret_cast<const float4*>(Wptr + k0 + 16 + 4);
        }
        const float* Asp = As[p];
        const float* Wsp = Ws[p];
        #pragma unroll
        for (int k = 0; k < 16; k++) {
            float4 ap = *reinterpret_cast<const float4*>(Asp + k * 68 + 4 * ty);
            ulonglong2 bn0 = *reinterpret_cast<const ulonglong2*>(Wsp + k * 132 + tx * 8);
            ulonglong2 bn1 = *reinterpret_cast<const ulonglong2*>(Wsp + k * 132 + tx * 8 + 4);
            ull bp[4] = {bn0.x, bn0.y, bn1.x, bn1.y};
            float aval[4] = {ap.x, ap.y, ap.z, ap.w};
            #pragma unroll
            for (int q = 0; q < 4; q++) {
                ull ax = pack2(aval[q], aval[q]);
                #pragma unroll
                for (int np = 0; np < 4; np++) fma2(acc[q][np], ax, bp[np]);
            }
        }
        if (more) {
            int q = p ^ 1;
            As[q][(aq + 0) * 68 + am] = a0.x; As[q][(aq + 1) * 68 + am] = a0.y;
            As[q][(aq + 2) * 68 + am] = a0.z; As[q][(aq + 3) * 68 + am] = a0.w;
            Ws[q][(lq + 0) * 132 + lm] = w0.x; Ws[q][(lq + 1) * 132 + lm] = w0.y;
            Ws[q][(lq + 2) * 132 + lm] = w0.z; Ws[q][(lq + 3) * 132 + lm] = w0.w;
            Ws[q][(lq + 4) * 132 + lm] = w1.x; Ws[q][(lq + 5) * 132 + lm] = w1.y;
            Ws[q][(lq + 6) * 132 + lm] = w1.z; Ws[q][(lq + 7) * 132 + lm] = w1.w;
            __syncthreads();
            p = q;
        }
    }

    #pragma unroll
    for (int r = 0; r < 4; r++) {
        int m = m0 + 4 * ty + r;
        float cv[8];
        #pragma unroll
        for (int np = 0; np < 4; np++) {
            float2 pv = unpack2(acc[r][np]);
            cv[2 * np]     = pv.x + bias[tx * 8 + 2 * np];
            cv[2 * np + 1] = pv.y + bias[tx * 8 + 2 * np + 1];
        }
        float4 s0 = make_float4(cv[0], cv[1], cv[2], cv[3]);
        float4 s1 = make_float4(cv[4], cv[5], cv[6], cv[7]);
        *reinterpret_cast<float4*>(C + (size_t)m * 128 + tx * 8)     = s0;
        *reinterpret_cast<float4*>(C + (size_t)m * 128 + tx * 8 + 4) = s1;
    }
}

// ---------------- persistent GRU scan (exact R14 structure) ----------------
extern __shared__ float smem_dyn[];

__global__ void __launch_bounds__(SCAN_THREADS, 1)
k_gru_scan(const float* __restrict__ giT,  // [T][G][B]
           const float* __restrict__ Wh,   // [G, H]
           const float* __restrict__ bh,   // [G]
           float* __restrict__ hT)         // [(T+1), H, B]
{
    float* ws  = smem_dyn;                     // [512][12] : ws[k*12 + c], c = g*4+jj
    float* red = ws + 512 * 12;                // [16][12][128]
    float* sbh = red + SCAN_WARPS * 12 * 128;  // [12]
    const int tid  = threadIdx.x;
    const int warp = tid >> 5;
    const int lane = tid & 31;
    const int j0   = blockIdx.x * 4;

    for (int i = tid; i < 12 * 512; i += SCAN_THREADS) {
        int c = i >> 9, k = i & 511;
        ws[k * 12 + c] = Wh[((size_t)((c >> 2) * H + j0 + (c & 3))) * H + k];
    }
    if (tid < 12) sbh[tid] = bh[(tid >> 2) * H + j0 + (tid & 3)];
    __syncthreads();

    const int k0 = warp * 32;
    const int bbase = lane * 4;
    const int gjj = tid >> 7;       // gate-phase j
    const int gb  = tid & 127;      // gate-phase b
    const float bias_r = sbh[gjj];
    const float bias_z = sbh[4 + gjj];
    const float bias_n = sbh[8 + gjj];

    for (int t = 0; t < T; t++) {
        const float* hprev = hT + (size_t)t * (H * B);

        size_t gibase = ((size_t)t * G + j0 + gjj) * B + gb;
        float ir  = giT[gibase];
        float iz  = giT[gibase + (size_t)H * B];
        float inn = giT[gibase + (size_t)2 * H * B];
        float hp  = hprev[(size_t)(j0 + gjj) * B + gb];

        ull acc[4][6];
        #pragma unroll
        for (int i = 0; i < 4; i++)
            #pragma unroll
            for (int cp = 0; cp < 6; cp++) acc[i][cp] = 0ull;

        #pragma unroll 4
        for (int kk = 0; kk < 32; kk++) {
            int k = k0 + kk;
            float4 hv = *reinterpret_cast<const float4*>(hprev + (size_t)k * B + bbase);
            ull h2[4];
            h2[0] = pack2(hv.x, hv.x);
            h2[1] = pack2(hv.y, hv.y);
            h2[2] = pack2(hv.z, hv.z);
            h2[3] = pack2(hv.w, hv.w);
            const float* wrow = ws + k * 12;
            #pragma unroll
            for (int cp = 0; cp < 6; cp++) {
                ull w2 = *reinterpret_cast<const ull*>(wrow + cp * 2);
                #pragma unroll
                for (int i = 0; i < 4; i++) fma2(acc[i][cp], h2[i], w2);
            }
        }

        #pragma unroll
        for (int cp = 0; cp < 6; cp++) {
            float2 v0 = unpack2(acc[0][cp]);
            float2 v1 = unpack2(acc[1][cp]);
            float2 v2 = unpack2(acc[2][cp]);
            float2 v3 = unpack2(acc[3][cp]);
            float4 a  = make_float4(v0.x, v1.x, v2.x, v3.x);
            float4 b4 = make_float4(v0.y, v1.y, v2.y, v3.y);
            *reinterpret_cast<float4*>(red + ((size_t)(warp * 12 + 2 * cp)) * B + bbase)     = a;
            *reinterpret_cast<float4*>(red + ((size_t)(warp * 12 + 2 * cp + 1)) * B + bbase) = b4;
        }
        __syncthreads();

        {
            float gr = 0.f, gz = 0.f, gn = 0.f;
            #pragma unroll
            for (int w = 0; w < SCAN_WARPS; w++) {
                gr += red[(w * 12 + 0 + gjj) * B + gb];
                gz += red[(w * 12 + 4 + gjj) * B + gb];
                gn += red[(w * 12 + 8 + gjj) * B + gb];
            }
            float r = fsigmoid_(ir + gr + bias_r);
            float u = fsigmoid_(iz + gz + bias_z);
            float n = ftanh_(inn + r * (gn + bias_n));
            hT[((size_t)(t + 1) * H + j0 + gjj) * B + gb] = (1.0f - u) * n + u * hp;
        }

        grid_barrier();
    }
}

// ---------------- encoder output: zm, zs, z, planar flow + kld_z partials ----------------
__global__ void k_flow_enc(const float* __restrict__ head,
                           const float* __restrict__ eps_enc,
                           const float* __restrict__ w_flow,
                           const float* __restrict__ b_flow,
                           const float* __restrict__ u_flow,
                           float* __restrict__ out,
                           float* __restrict__ z_all,
                           double* __restrict__ pz) {
    __shared__ float red[4][64];
    __shared__ double dred[256];
    int rl = threadIdx.x >> 6;
    int j = threadIdx.x & 63;
    int row = blockIdx.x * 4 + rl;       // t*B + b
    int t = row >> 7;
    int b = row & 127;

    float zm = fsigmoid_(head[row * 128 + j]);
    float zs = fsoftplus_(head[row * 128 + 64 + j]);
    float eps = eps_enc[b * (T * Z) + t * Z + j];
    float z = eps * zs + zm;

    #pragma unroll
    for (int k = 0; k < KF; k++) {
        red[rl][j] = z * w_flow[(t * KF + k) * Z + j];
        __syncthreads();
        #pragma unroll
        for (int s = 32; s > 0; s >>= 1) {
            if (j < s) red[rl][j] += red[rl][j + s];
            __syncthreads();
        }
        float sv = red[rl][0] + b_flow[t * KF + k];
        __syncthreads();
        z += u_flow[(t * KF + k) * Z + j] * ftanh_(sv);
    }

    int o = (b * T + t) * Z + j;
    out[2 + o]         = z;
    out[2 + S + o]     = zm;
    out[2 + 2 * S + o] = zs;
    z_all[row * Z + j] = z;

    float ez = __expf(zs);
    dred[threadIdx.x] = 1.0 + (double)zs - (double)zm * (double)zm - (double)ez;
    __syncthreads();
    for (int s = 128; s > 0; s >>= 1) {
        if (threadIdx.x < s) dred[threadIdx.x] += dred[threadIdx.x + s];
        __syncthreads();
    }
    if (threadIdx.x == 0) pz[blockIdx.x] = dred[0];
}

// ---------------- decoder output + nll/kld_x partials ----------------
__global__ void k_dec_out(const float* __restrict__ head,
                          const float* __restrict__ eps_dec,
                          const float* __restrict__ x,
                          float* __restrict__ out,
                          double* __restrict__ pn,
                          double* __restrict__ px) {
    __shared__ double sn[256];
    __shared__ double sk[256];
    int i = blockIdx.x * blockDim.x + threadIdx.x;
    int row = i >> 6;
    int j = i & 63;
    int t = row >> 7;
    int b = row & 127;
    float xm = fsigmoid_(head[row * 128 + j]);
    float xs = fsoftplus_(head[row * 128 + 64 + j]);
    int src = b * (T * Xd) + t * Xd + j;
    float eps = eps_dec[src];
    float xo = eps * xs + xm;
    int o = (b * T + t) * Xd + j;
    out[2 + 3 * S + o] = xo;
    out[2 + 4 * S + o] = xm;
    out[2 + 5 * S + o] = xs;

    float xv = x[src];
    float dq = (xv - xm) * __expf(-0.5f * xs);
    float ex = __expf(xs);
    sn[threadIdx.x] = (double)xs + (double)dq * (double)dq;
    sk[threadIdx.x] = 1.0 + (double)xs - (double)xm * (double)xm - (double)ex;
    __syncthreads();
    for (int s = 128; s > 0; s >>= 1) {
        if (threadIdx.x < s) {
            sn[threadIdx.x] += sn[threadIdx.x + s];
            sk[threadIdx.x] += sk[threadIdx.x + s];
        }
        __syncthreads();
    }
    if (threadIdx.x == 0) {
        pn[blockIdx.x] = sn[0];
        px[blockIdx.x] = sk[0];
    }
}

// ---------------- final deterministic reduction ----------------
__global__ void k_reduce_final(const double* __restrict__ pz,
                               const double* __restrict__ pn,
                               const double* __restrict__ px,
                               float* __restrict__ out) {
    __shared__ double sn[256];
    __shared__ double sk[256];
    double an = 0.0, ak = 0.0;
    for (int i = threadIdx.x; i < 2048; i += 256) {
        an += pn[i];
        ak += pz[i] + px[i];
    }
    sn[threadIdx.x] = an;
    sk[threadIdx.x] = ak;
    __syncthreads();
    for (int s = 128; s > 0; s >>= 1) {
        if (threadIdx.x < s) {
            sn[threadIdx.x] += sn[threadIdx.x + s];
            sk[threadIdx.x] += sk[threadIdx.x + s];
        }
        __syncthreads();
    }
    if (threadIdx.x == 0) {
        out[0] = (float)(0.5 * sn[0]);
        out[1] = (float)(-0.5 * sk[0]);
    }
}

// ---------------- launch ----------------
extern "C" void kernel_launch(void* const* d_in, const int* in_sizes, int n_in,
                              void* d_out, int out_size) {
    const float* x        = (const float*)d_in[0];
    const float* eps_enc  = (const float*)d_in[1];
    const float* eps_dec  = (const float*)d_in[2];
    const float* Wi_enc   = (const float*)d_in[3];
    const float* Wh_enc   = (const float*)d_in[4];
    const float* bi_enc   = (const float*)d_in[5];
    const float* bh_enc   = (const float*)d_in[6];
    const float* Wphi_enc = (const float*)d_in[7];
    const float* bphi_enc = (const float*)d_in[8];
    const float* W_zmean  = (const float*)d_in[9];
    const float* b_zmean  = (const float*)d_in[10];
    const float* W_zstd   = (const float*)d_in[11];
    const float* b_zstd   = (const float*)d_in[12];
    const float* w_flow   = (const float*)d_in[13];
    const float* b_flow   = (const float*)d_in[14];
    const float* u_flow   = (const float*)d_in[15];
    const float* Wi_dec   = (const float*)d_in[16];
    const float* Wh_dec   = (const float*)d_in[17];
    const float* bi_dec   = (const float*)d_in[18];
    const float* bh_dec   = (const float*)d_in[19];
    const float* Wphi_dec = (const float*)d_in[20];
    const float* bphi_dec = (const float*)d_in[21];
    const float* W_xmean  = (const float*)d_in[22];
    const float* b_xmean  = (const float*)d_in[23];
    const float* W_xstd   = (const float*)d_in[24];
    const float* b_xstd   = (const float*)d_in[25];
    float* out = (float*)d_out;

    float *p_xT, *p_gi, *p_h, *p_phi, *p_head, *p_z;
    float *p_WhZ, *p_bhZ, *p_WhX, *p_bhX;
    double *p_pz, *p_pn, *p_px;
    cudaGetSymbolAddress((void**)&p_xT,   g_xT);
    cudaGetSymbolAddress((void**)&p_gi,   g_gi);
    cudaGetSymbolAddress((void**)&p_h,    g_h);
    cudaGetSymbolAddress((void**)&p_phi,  g_phi);
    cudaGetSymbolAddress((void**)&p_head, g_head);
    cudaGetSymbolAddress((void**)&p_z,    g_z);
    cudaGetSymbolAddress((void**)&p_WhZ,  g_WheadZ);
    cudaGetSymbolAddress((void**)&p_bhZ,  g_bheadZ);
    cudaGetSymbolAddress((void**)&p_WhX,  g_WheadX);
    cudaGetSymbolAddress((void**)&p_bhX,  g_bheadX);
    cudaGetSymbolAddress((void**)&p_pz,   g_pz);
    cudaGetSymbolAddress((void**)&p_pn,   g_pn);
    cudaGetSymbolAddress((void**)&p_px,   g_px);

    cudaFuncSetAttribute(k_gru_scan, cudaFuncAttributeMaxDynamicSharedMemorySize, SCAN_SMEM);
    cudaFuncSetAttribute(k_gemm,    cudaFuncAttributeMaxDynamicSharedMemorySize, GEMM_SMEM);
    cudaFuncSetAttribute(k_gemm_ht, cudaFuncAttributeMaxDynamicSharedMemorySize, GEMM_SMEM);

    // 0) fused prep
    k_prep<<<(721152 + 255) / 256, 256>>>(x, W_zmean, b_zmean, W_zstd, b_zstd,
                                          W_xmean, b_xmean, W_xstd, b_xstd,
                                          p_xT, p_h, p_WhZ, p_bhZ, p_WhX, p_bhX);

    // 1) gi_enc -> transposed [t][col][b]
    {
        dim3 grid(BT / 128, G / 128);
        k_gemm<<<grid, 256, GEMM_SMEM>>>(p_xT, Xd, Wi_enc, Xd, bi_enc, p_gi, G, Xd, 0, 1);
    }
    // 2) encoder GRU scan
    k_gru_scan<<<NBLK, SCAN_THREADS, SCAN_SMEM>>>(p_gi, Wh_enc, bh_enc, p_h);

    // 3) phi_enc
    {
        dim3 grid(BT / 128, D / 128);
        k_gemm_ht<<<grid, 256, GEMM_SMEM>>>(p_h, Wphi_enc, H + Z, bphi_enc, p_phi, D, H, 1);
    }
    // 4) z heads (64-row tiles, 128 blocks)
    k_gemm_h64<<<BT / 64, 256>>>(p_phi, p_WhZ, p_bhZ, p_head);

    // 5) flow + z outputs + kld_z partials
    k_flow_enc<<<BT / 4, 256>>>(p_head, eps_enc, w_flow, b_flow, u_flow, out, p_z, p_pz);

    // 6) gi_dec -> transposed
    {
        dim3 grid(BT / 128, G / 128);
        k_gemm<<<grid, 256, GEMM_SMEM>>>(p_z, Z, Wi_dec, Z, bi_dec, p_gi, G, Z, 0, 1);
    }
    // 7) decoder GRU scan
    k_gru_scan<<<NBLK, SCAN_THREADS, SCAN_SMEM>>>(p_gi, Wh_dec, bh_dec, p_h);

    // 8) phi_dec
    {
        dim3 grid(BT / 128, D / 128);
        k_gemm_ht<<<grid, 256, GEMM_SMEM>>>(p_h, Wphi_dec, H, bphi_dec, p_phi, D, H, 1);
    }
    // 9) x heads (64-row tiles)
    k_gemm_h64<<<BT / 64, 256>>>(p_phi, p_WhX, p_bhX, p_head);

    // 10) decoder outputs + nll/kld_x partials
    k_dec_out<<<S / 256, 256>>>(p_head, eps_dec, x, out, p_pn, p_px);

    // 11) final reduction
    k_reduce_final<<<1, 256>>>(p_pz, p_pn, p_px, out);
}